// round 1
// baseline (speedup 1.0000x reference)
#include <cuda_runtime.h>
#include <cstdint>

#define W_ 12
#define N_ 20000
#define C_ 64
#define E_ 320000
#define TOT (W_*N_*C_)   // 15,360,000 floats

// ---------------- scratch (device globals: no allocation allowed) ----------
__device__ __align__(128) float g_Wc[7*64*128];   // combined inception weights [tap][cin][lane128]
__device__ __align__(128) float g_bc[128];        // combined biases per lane
__device__ __align__(128) float g_H  [TOT];       // h buffer (W,N,C)
__device__ __align__(128) float g_T  [TOT];       // transformed h
__device__ __align__(128) float g_Agg[TOT];       // segment-sum accumulator

struct WPtrs {
    const float* sw[4]; const float* sb[4];
    const float* gw[4]; const float* gb[4];
};

// ---------------- K0: build combined weights --------------------------------
// lane j in [0,128): kw=j>>5 selects kernel (k=2*kw+1), half=(j>>4)&1 (0=sig,1=gate),
// ch=j&15 is the 16-wide output slice of that kernel.
__global__ void prep_kernel(WPtrs p) {
    int gid = blockIdx.x * blockDim.x + threadIdx.x;
    if (gid < 7*64*128) {
        int j    = gid & 127;
        int rest = gid >> 7;
        int i    = rest & 63;   // cin
        int t    = rest >> 6;   // tap 0..6
        int kw   = j >> 5;
        int half = (j >> 4) & 1;
        int ch   = j & 15;
        int k    = 2*kw + 1;
        float v = 0.f;
        if (t < k) {
            const float* src = half ? p.gw[kw] : p.sw[kw];
            v = src[(ch*64 + i)*k + t];
        }
        g_Wc[gid] = v;
    }
    if (gid < 128) {
        int j = gid;
        int kw = j >> 5; int half = (j >> 4) & 1; int ch = j & 15;
        g_bc[j] = half ? p.gb[kw][ch] : p.sb[kw][ch];
    }
}

// ---------------- K1: inception + gated activation -------------------------
template<int K>
__device__ __forceinline__ void incep_body(const float xs[2][64][18], int j, int base,
                                           float acc0[12], float acc1[12]) {
    #pragma unroll 1
    for (int i = 0; i < 64; i++) {
        float xr0[11+K], xr1[11+K];
        #pragma unroll
        for (int m = 0; m < 11+K; m++) {
            xr0[m] = xs[0][i][base+m];
            xr1[m] = xs[1][i][base+m];
        }
        const float* wp = g_Wc + i*128 + j;
        #pragma unroll
        for (int t = 0; t < K; t++) {
            float wv = __ldg(wp + t*64*128);
            #pragma unroll
            for (int w = 0; w < 12; w++) {
                acc0[w] = fmaf(wv, xr0[w+t], acc0[w]);
                acc1[w] = fmaf(wv, xr1[w+t], acc1[w]);
            }
        }
    }
}

__global__ void __launch_bounds__(128) incep_kernel(const float* __restrict__ x) {
    __shared__ float xs[2][64][18];   // padded temporal window, 2 nodes
    int tid = threadIdx.x;
    int n0  = blockIdx.x * 2;

    for (int idx = tid; idx < 2*64*18; idx += 128) ((float*)xs)[idx] = 0.f;
    __syncthreads();
    {
        int c = tid & 63, nn = tid >> 6;
        int n = n0 + nn;
        #pragma unroll
        for (int w = 0; w < 12; w++)
            xs[nn][c][w+3] = x[((size_t)w*N_ + n)*64 + c];
    }
    __syncthreads();

    int lane = tid & 31;
    // rotate kernel assignment across warps/blocks to balance FMA load over SMSPs
    int kw   = (((tid >> 5) + blockIdx.x) & 3);
    int j    = kw*32 + lane;
    int half = (lane >> 4) & 1;
    int ch   = lane & 15;
    int base = 3 - kw;     // = 3 - (k-1)/2

    float acc0[12], acc1[12];
    float b = g_bc[j];
    #pragma unroll
    for (int w = 0; w < 12; w++) { acc0[w] = b; acc1[w] = b; }

    if      (kw == 0) incep_body<1>(xs, j, base, acc0, acc1);
    else if (kw == 1) incep_body<3>(xs, j, base, acc0, acc1);
    else if (kw == 2) incep_body<5>(xs, j, base, acc0, acc1);
    else              incep_body<7>(xs, j, base, acc0, acc1);

    int cout = kw*16 + ch;
    #pragma unroll
    for (int w = 0; w < 12; w++) {
        float g0 = __shfl_down_sync(0xffffffffu, acc0[w], 16);
        float g1 = __shfl_down_sync(0xffffffffu, acc1[w], 16);
        if (half == 0) {
            float s0 = fmaxf(acc0[w], 0.f) * (1.f / (1.f + __expf(-g0)));
            float s1 = fmaxf(acc1[w], 0.f) * (1.f / (1.f + __expf(-g1)));
            g_H[((size_t)w*N_ + n0    )*64 + cout] = s0;
            g_H[((size_t)w*N_ + n0 + 1)*64 + cout] = s1;
        }
    }
}

// ---------------- K2: per-window dense transform T = H @ Wg ----------------
__global__ void __launch_bounds__(256) gemm_kernel(const float* __restrict__ gw, int hop) {
    __shared__ float4 Wsh[64*16];     // [cin][cout/4]
    int w = blockIdx.y;
    const float4* Wg = (const float4*)(gw + ((size_t)(hop*W_ + w))*64*64);
    for (int idx = threadIdx.x; idx < 1024; idx += 256) Wsh[idx] = Wg[idx];
    __syncthreads();

    int n = blockIdx.x*256 + threadIdx.x;
    if (n >= N_) return;
    const float4* Hr = (const float4*)g_H + ((size_t)w*N_ + n)*16;
    float h[64];
    #pragma unroll
    for (int i4 = 0; i4 < 16; i4++) {
        float4 v = Hr[i4];
        h[i4*4+0]=v.x; h[i4*4+1]=v.y; h[i4*4+2]=v.z; h[i4*4+3]=v.w;
    }
    float4* Tr = (float4*)g_T + ((size_t)w*N_ + n)*16;
    #pragma unroll 1
    for (int o4 = 0; o4 < 16; o4++) {
        float4 a = make_float4(0.f,0.f,0.f,0.f);
        #pragma unroll
        for (int i = 0; i < 64; i++) {
            float4 wv = Wsh[i*16 + o4];
            a.x = fmaf(h[i], wv.x, a.x);
            a.y = fmaf(h[i], wv.y, a.y);
            a.z = fmaf(h[i], wv.z, a.z);
            a.w = fmaf(h[i], wv.w, a.w);
        }
        Tr[o4] = a;
    }
}

// ---------------- K3: zero Agg ----------------------------------------------
__global__ void zero_kernel() {
    int i = blockIdx.x*blockDim.x + threadIdx.x;
    if (i < TOT/4) ((float4*)g_Agg)[i] = make_float4(0.f,0.f,0.f,0.f);
}

// ---------------- K4: edge scatter with vector reductions ------------------
__device__ __forceinline__ void red4(float* p, float a, float b, float c, float d) {
    unsigned long long ga = (unsigned long long)__cvta_generic_to_global(p);
    asm volatile("red.global.add.v4.f32 [%0], {%1,%2,%3,%4};"
                 :: "l"(ga), "f"(a), "f"(b), "f"(c), "f"(d) : "memory");
}

__global__ void scatter_kernel(const int* __restrict__ ei, const float* __restrict__ ewt) {
    int g = blockIdx.x*blockDim.x + threadIdx.x;
    if (g >= W_*E_*4) return;
    int q  = g & 3;          // 16-channel chunk
    int el = g >> 2;
    int w  = el / E_;
    int e  = el - w*E_;
    int src = ei[(size_t)(2*w)  *E_ + e];
    int dst = ei[(size_t)(2*w+1)*E_ + e];
    float wt = ewt[(size_t)w*E_ + e];
    const float4* Ts = (const float4*)g_T + ((size_t)w*N_ + src)*16 + q*4;
    float4 v0 = Ts[0], v1 = Ts[1], v2 = Ts[2], v3 = Ts[3];
    float* Ag = g_Agg + ((size_t)w*N_ + dst)*64 + q*16;
    red4(Ag +  0, wt*v0.x, wt*v0.y, wt*v0.z, wt*v0.w);
    red4(Ag +  4, wt*v1.x, wt*v1.y, wt*v1.z, wt*v1.w);
    red4(Ag +  8, wt*v2.x, wt*v2.y, wt*v2.z, wt*v2.w);
    red4(Ag + 12, wt*v3.x, wt*v3.y, wt*v3.z, wt*v3.w);
}

// ---------------- K5: bias + ELU (+ residual on last hop) ------------------
__device__ __forceinline__ float elu1(float v) { return v > 0.f ? v : expm1f(v); }

__global__ void elu_kernel(const float* __restrict__ gb, int hop,
                           const float* __restrict__ x, float* __restrict__ out) {
    int i = blockIdx.x*blockDim.x + threadIdx.x;
    if (i >= TOT/4) return;
    int w  = i / (N_*16);
    int c4 = i & 15;
    float4 a = ((const float4*)g_Agg)[i];
    float4 b = *((const float4*)(gb + ((size_t)(hop*W_ + w))*64) + c4);
    a.x = elu1(a.x + b.x);
    a.y = elu1(a.y + b.y);
    a.z = elu1(a.z + b.z);
    a.w = elu1(a.w + b.w);
    if (out) {
        float4 xv = ((const float4*)x)[i];
        a.x += xv.x; a.y += xv.y; a.z += xv.z; a.w += xv.w;
        ((float4*)out)[i] = a;
    } else {
        ((float4*)g_H)[i] = a;
    }
}

// ---------------- launch -----------------------------------------------------
extern "C" void kernel_launch(void* const* d_in, const int* in_sizes, int n_in,
                              void* d_out, int out_size) {
    const float* x  = (const float*)d_in[0];
    const int*   ei = (const int*)  d_in[1];
    const float* ew = (const float*)d_in[2];

    WPtrs p;
    if (in_sizes[5] == 1024) {
        // dict order: sw{k}, sb{k}, gw{k}, gb{k} per kernel size
        int idx = 3;
        for (int t = 0; t < 4; t++) {
            p.sw[t] = (const float*)d_in[idx++];
            p.sb[t] = (const float*)d_in[idx++];
            p.gw[t] = (const float*)d_in[idx++];
            p.gb[t] = (const float*)d_in[idx++];
        }
    } else {
        // signature order: sw1,sb1,sw3,sb3,... then gw1,gb1,...
        int idx = 3;
        for (int t = 0; t < 4; t++) {
            p.sw[t] = (const float*)d_in[idx++];
            p.sb[t] = (const float*)d_in[idx++];
        }
        for (int t = 0; t < 4; t++) {
            p.gw[t] = (const float*)d_in[idx++];
            p.gb[t] = (const float*)d_in[idx++];
        }
    }
    const float* gw = (const float*)d_in[19];
    const float* gb = (const float*)d_in[20];
    float* out = (float*)d_out;

    prep_kernel<<<(7*64*128 + 255)/256, 256>>>(p);
    incep_kernel<<<N_/2, 128>>>(x);
    for (int hop = 0; hop < 2; hop++) {
        zero_kernel<<<(TOT/4 + 255)/256, 256>>>();
        gemm_kernel<<<dim3((N_ + 255)/256, W_), 256>>>(gw, hop);
        scatter_kernel<<<(W_*E_*4 + 255)/256, 256>>>(ei, ew);
        elu_kernel<<<(TOT/4 + 255)/256, 256>>>(gb, hop, x, hop == 1 ? out : nullptr);
    }
}

// round 2
// speedup vs baseline: 1.2032x; 1.2032x over previous
#include <cuda_runtime.h>
#include <cstdint>

#define W_ 12
#define N_ 20000
#define C_ 64
#define E_ 320000
#define TOT (W_*N_*C_)   // 15,360,000 floats

// ---------------- scratch (device globals) ----------------------------------
__device__ __align__(128) float2 g_Wc2[7*64*128];  // duplicated inception weights [tap][cin][lane]
__device__ __align__(128) float  g_bc[128];
__device__ __align__(128) float  g_H  [TOT];       // h buffer (W,N,C)
__device__ __align__(128) float  g_T  [TOT];       // transformed h
__device__ int   g_deg   [W_*N_];
__device__ int   g_rowptr[W_*N_];
__device__ int   g_cur   [W_*N_];
__device__ int   g_esrc  [W_*E_];
__device__ float g_ewt2  [W_*E_];

struct WPtrs {
    const float* sw[4]; const float* sb[4];
    const float* gw[4]; const float* gb[4];
};

typedef unsigned long long ull;

__device__ __forceinline__ void ffma2(ull& d, ull a, ull b) {
    asm("fma.rn.f32x2 %0, %1, %2, %0;" : "+l"(d) : "l"(a), "l"(b));
}

// ---------------- K0: build combined (duplicated) weights -------------------
__global__ void prep_kernel(WPtrs p) {
    int gid = blockIdx.x * blockDim.x + threadIdx.x;
    if (gid < 7*64*128) {
        int j    = gid & 127;
        int rest = gid >> 7;
        int i    = rest & 63;   // cin
        int t    = rest >> 6;   // tap 0..6
        int kw   = j >> 5;
        int half = (j >> 4) & 1;
        int ch   = j & 15;
        int k    = 2*kw + 1;
        float v = 0.f;
        if (t < k) {
            const float* src = half ? p.gw[kw] : p.sw[kw];
            v = src[(ch*64 + i)*k + t];
        }
        g_Wc2[gid] = make_float2(v, v);
    }
    if (gid < 128) {
        int j = gid;
        int kw = j >> 5; int half = (j >> 4) & 1; int ch = j & 15;
        g_bc[j] = half ? p.gb[kw][ch] : p.sb[kw][ch];
    }
}

// ---------------- K1: inception + gated activation (f32x2) ------------------
template<int K>
__device__ __forceinline__ void incep_body(const float2 (&xs)[64][18], int j, int base,
                                           ull acc[12]) {
    #pragma unroll 1
    for (int i = 0; i < 64; i++) {
        ull xr[11+K];
        #pragma unroll
        for (int m = 0; m < 11+K; m++)
            xr[m] = *(const ull*)&xs[i][base+m];
        const ull* wp = (const ull*)(g_Wc2 + i*128 + j);
        #pragma unroll
        for (int t = 0; t < K; t++) {
            ull wv = __ldg(wp + (size_t)t*64*128);
            #pragma unroll
            for (int w = 0; w < 12; w++)
                ffma2(acc[w], xr[w+t], wv);
        }
    }
}

__global__ void __launch_bounds__(128) incep_kernel(const float* __restrict__ x) {
    __shared__ float2 xs[64][18];   // padded temporal window, (node0,node1) packed
    int tid = threadIdx.x;
    int n0  = blockIdx.x * 2;

    for (int idx = tid; idx < 64*18*2; idx += 128) ((float*)xs)[idx] = 0.f;
    __syncthreads();
    {
        int c = tid & 63, nn = tid >> 6;
        int n = n0 + nn;
        #pragma unroll
        for (int w = 0; w < 12; w++)
            ((float*)&xs[c][w+3])[nn] = x[((size_t)w*N_ + n)*64 + c];
    }
    __syncthreads();

    int lane = tid & 31;
    int kw   = (((tid >> 5) + blockIdx.x) & 3);  // rotate kernel size over warps
    int j    = kw*32 + lane;
    int half = (lane >> 4) & 1;
    int ch   = lane & 15;
    int base = 3 - kw;

    ull acc[12];
    float b = g_bc[j];
    float2 binit = make_float2(b, b);
    #pragma unroll
    for (int w = 0; w < 12; w++) acc[w] = *(ull*)&binit;

    if      (kw == 0) incep_body<1>(xs, j, base, acc);
    else if (kw == 1) incep_body<3>(xs, j, base, acc);
    else if (kw == 2) incep_body<5>(xs, j, base, acc);
    else              incep_body<7>(xs, j, base, acc);

    int cout = kw*16 + ch;
    #pragma unroll
    for (int w = 0; w < 12; w++) {
        ull gz = __shfl_down_sync(0xffffffffu, acc[w], 16);
        if (half == 0) {
            float2 a = *(float2*)&acc[w];
            float2 g = *(float2*)&gz;
            float s0 = fmaxf(a.x, 0.f) * (1.f / (1.f + __expf(-g.x)));
            float s1 = fmaxf(a.y, 0.f) * (1.f / (1.f + __expf(-g.y)));
            g_H[((size_t)w*N_ + n0    )*64 + cout] = s0;
            g_H[((size_t)w*N_ + n0 + 1)*64 + cout] = s1;
        }
    }
}

// ---------------- K2: per-window dense transform T = H @ Wg ----------------
// i-outer / o-inner: acc reuse distance ~40 instrs, no serial chain.
// 2 threads per node, 32 couts each.
__global__ void __launch_bounds__(256) gemm_kernel(const float* __restrict__ gw, int hop) {
    __shared__ float4 Wsh[64*16];     // [cin][cout/4]
    int w = blockIdx.y;
    const float4* Wg = (const float4*)(gw + ((size_t)(hop*W_ + w))*64*64);
    for (int idx = threadIdx.x; idx < 1024; idx += 256) Wsh[idx] = Wg[idx];
    __syncthreads();

    int n  = blockIdx.x*128 + (threadIdx.x >> 1);
    int oh = threadIdx.x & 1;
    if (n >= N_) return;
    const float4* Hr = (const float4*)g_H + ((size_t)w*N_ + n)*16;
    float h[64];
    #pragma unroll
    for (int i4 = 0; i4 < 16; i4++) {
        float4 v = Hr[i4];
        h[i4*4+0]=v.x; h[i4*4+1]=v.y; h[i4*4+2]=v.z; h[i4*4+3]=v.w;
    }
    float4 acc[8];
    #pragma unroll
    for (int p = 0; p < 8; p++) acc[p] = make_float4(0.f,0.f,0.f,0.f);

    #pragma unroll 1
    for (int i = 0; i < 64; i++) {
        float hv = h[i];
        const float4* wr = &Wsh[i*16 + oh*8];
        #pragma unroll
        for (int p = 0; p < 8; p++) {
            float4 wv = wr[p];
            acc[p].x = fmaf(hv, wv.x, acc[p].x);
            acc[p].y = fmaf(hv, wv.y, acc[p].y);
            acc[p].z = fmaf(hv, wv.z, acc[p].z);
            acc[p].w = fmaf(hv, wv.w, acc[p].w);
        }
    }
    float4* Tr = (float4*)g_T + ((size_t)w*N_ + n)*16 + oh*8;
    #pragma unroll
    for (int p = 0; p < 8; p++) Tr[p] = acc[p];
}

// ---------------- CSR build (once; reused by both hops) --------------------
__global__ void zerodeg_kernel() {
    int i = blockIdx.x*blockDim.x + threadIdx.x;
    if (i < W_*N_) g_deg[i] = 0;
}

__global__ void hist_kernel(const int* __restrict__ ei) {
    int g = blockIdx.x*blockDim.x + threadIdx.x;
    if (g >= W_*E_) return;
    int w = g / E_;
    int e = g - w*E_;
    int dst = ei[(size_t)(2*w+1)*E_ + e];
    atomicAdd(&g_deg[w*N_ + dst], 1);
}

__global__ void __launch_bounds__(512) scan_kernel() {
    __shared__ int wsum[16];
    int w = blockIdx.x;
    int t = threadIdx.x, lane = t & 31, wid = t >> 5;
    const int* deg = g_deg + w*N_;
    int base = t * 40;                // 512*40 = 20480 >= 20000
    int s = 0;
    for (int k = 0; k < 40; k++) {
        int idx = base + k;
        if (idx < N_) s += deg[idx];
    }
    int v = s;
    #pragma unroll
    for (int d = 1; d < 32; d <<= 1) {
        int o = __shfl_up_sync(0xffffffffu, v, d);
        if (lane >= d) v += o;
    }
    if (lane == 31) wsum[wid] = v;
    __syncthreads();
    if (t == 0) {
        int r = 0;
        #pragma unroll
        for (int q = 0; q < 16; q++) { int xq = wsum[q]; wsum[q] = r; r += xq; }
    }
    __syncthreads();
    int run = wsum[wid] + (v - s);
    for (int k = 0; k < 40; k++) {
        int idx = base + k;
        if (idx < N_) {
            int d = deg[idx];
            g_rowptr[w*N_ + idx] = run;
            g_cur   [w*N_ + idx] = run;
            run += d;
        }
    }
}

__global__ void place_kernel(const int* __restrict__ ei, const float* __restrict__ ewt) {
    int g = blockIdx.x*blockDim.x + threadIdx.x;
    if (g >= W_*E_) return;
    int w = g / E_;
    int e = g - w*E_;
    int src = ei[(size_t)(2*w)  *E_ + e];
    int dst = ei[(size_t)(2*w+1)*E_ + e];
    float wt = ewt[(size_t)w*E_ + e];
    int pos = atomicAdd(&g_cur[w*N_ + dst], 1);
    g_esrc[(size_t)w*E_ + pos] = src;
    g_ewt2[(size_t)w*E_ + pos] = wt;
}

// ---------------- K4: gather-aggregate + bias + ELU (+residual) -------------
__device__ __forceinline__ float elu1(float v) { return v > 0.f ? v : expm1f(v); }

__global__ void __launch_bounds__(256) agg_kernel(const float* __restrict__ gb, int hop,
                                                  const float* __restrict__ x,
                                                  float* __restrict__ out) {
    int g = blockIdx.x*256 + threadIdx.x;
    if (g >= W_*N_*4) return;
    int q  = g & 3;          // 16-channel quarter
    int wn = g >> 2;         // w*N_ + n
    int w  = wn / N_;

    int beg = g_rowptr[wn];
    int end = beg + g_deg[wn];
    const int*    es = g_esrc + (size_t)w*E_;
    const float*  ep = g_ewt2 + (size_t)w*E_;
    const float4* Tb = (const float4*)g_T + (size_t)w*N_*16 + q*4;

    float4 a0 = make_float4(0,0,0,0), a1 = a0, a2 = a0, a3 = a0;
    #pragma unroll 2
    for (int e = beg; e < end; e++) {
        int   s  = es[e];
        float wt = ep[e];
        const float4* Ts = Tb + (size_t)s*16;
        float4 v0 = Ts[0], v1 = Ts[1], v2 = Ts[2], v3 = Ts[3];
        a0.x = fmaf(wt, v0.x, a0.x); a0.y = fmaf(wt, v0.y, a0.y);
        a0.z = fmaf(wt, v0.z, a0.z); a0.w = fmaf(wt, v0.w, a0.w);
        a1.x = fmaf(wt, v1.x, a1.x); a1.y = fmaf(wt, v1.y, a1.y);
        a1.z = fmaf(wt, v1.z, a1.z); a1.w = fmaf(wt, v1.w, a1.w);
        a2.x = fmaf(wt, v2.x, a2.x); a2.y = fmaf(wt, v2.y, a2.y);
        a2.z = fmaf(wt, v2.z, a2.z); a2.w = fmaf(wt, v2.w, a2.w);
        a3.x = fmaf(wt, v3.x, a3.x); a3.y = fmaf(wt, v3.y, a3.y);
        a3.z = fmaf(wt, v3.z, a3.z); a3.w = fmaf(wt, v3.w, a3.w);
    }

    const float4* bb = (const float4*)(gb + ((size_t)(hop*W_ + w))*64) + q*4;
    float4 b0 = bb[0], b1 = bb[1], b2 = bb[2], b3 = bb[3];
    a0.x = elu1(a0.x+b0.x); a0.y = elu1(a0.y+b0.y); a0.z = elu1(a0.z+b0.z); a0.w = elu1(a0.w+b0.w);
    a1.x = elu1(a1.x+b1.x); a1.y = elu1(a1.y+b1.y); a1.z = elu1(a1.z+b1.z); a1.w = elu1(a1.w+b1.w);
    a2.x = elu1(a2.x+b2.x); a2.y = elu1(a2.y+b2.y); a2.z = elu1(a2.z+b2.z); a2.w = elu1(a2.w+b2.w);
    a3.x = elu1(a3.x+b3.x); a3.y = elu1(a3.y+b3.y); a3.z = elu1(a3.z+b3.z); a3.w = elu1(a3.w+b3.w);

    size_t oi = (size_t)wn*16 + q*4;
    if (out) {
        const float4* xv = (const float4*)x + oi;
        float4 x0 = xv[0], x1 = xv[1], x2 = xv[2], x3 = xv[3];
        a0.x+=x0.x; a0.y+=x0.y; a0.z+=x0.z; a0.w+=x0.w;
        a1.x+=x1.x; a1.y+=x1.y; a1.z+=x1.z; a1.w+=x1.w;
        a2.x+=x2.x; a2.y+=x2.y; a2.z+=x2.z; a2.w+=x2.w;
        a3.x+=x3.x; a3.y+=x3.y; a3.z+=x3.z; a3.w+=x3.w;
        float4* o = (float4*)out + oi;
        o[0]=a0; o[1]=a1; o[2]=a2; o[3]=a3;
    } else {
        float4* o = (float4*)g_H + oi;
        o[0]=a0; o[1]=a1; o[2]=a2; o[3]=a3;
    }
}

// ---------------- launch -----------------------------------------------------
extern "C" void kernel_launch(void* const* d_in, const int* in_sizes, int n_in,
                              void* d_out, int out_size) {
    const float* x  = (const float*)d_in[0];
    const int*   ei = (const int*)  d_in[1];
    const float* ew = (const float*)d_in[2];

    WPtrs p;
    if (in_sizes[5] == 1024) {
        int idx = 3;
        for (int t = 0; t < 4; t++) {
            p.sw[t] = (const float*)d_in[idx++];
            p.sb[t] = (const float*)d_in[idx++];
            p.gw[t] = (const float*)d_in[idx++];
            p.gb[t] = (const float*)d_in[idx++];
        }
    } else {
        int idx = 3;
        for (int t = 0; t < 4; t++) {
            p.sw[t] = (const float*)d_in[idx++];
            p.sb[t] = (const float*)d_in[idx++];
        }
        for (int t = 0; t < 4; t++) {
            p.gw[t] = (const float*)d_in[idx++];
            p.gb[t] = (const float*)d_in[idx++];
        }
    }
    const float* gw = (const float*)d_in[19];
    const float* gb = (const float*)d_in[20];
    float* out = (float*)d_out;

    prep_kernel<<<(7*64*128 + 255)/256, 256>>>(p);
    incep_kernel<<<N_/2, 128>>>(x);

    // CSR build (edge structure identical for both hops)
    zerodeg_kernel<<<(W_*N_ + 255)/256, 256>>>();
    hist_kernel<<<(W_*E_ + 255)/256, 256>>>(ei);
    scan_kernel<<<W_, 512>>>();
    place_kernel<<<(W_*E_ + 255)/256, 256>>>(ei, ew);

    for (int hop = 0; hop < 2; hop++) {
        gemm_kernel<<<dim3((N_ + 127)/128, W_), 256>>>(gw, hop);
        agg_kernel<<<(W_*N_*4 + 255)/256, 256>>>(gb, hop, x, hop == 1 ? out : nullptr);
    }
}

// round 4
// speedup vs baseline: 1.3985x; 1.1623x over previous
#include <cuda_runtime.h>
#include <cstdint>

#define W_ 12
#define N_ 20000
#define C_ 64
#define E_ 320000
#define TOT (W_*N_*C_)   // 15,360,000 floats
typedef unsigned long long ull;
typedef unsigned int uint;

// ---------------- scratch (device globals) ----------------------------------
__device__ __align__(128) ull   g_Wp[7*128*32];   // tf32-packed inception weights [t][lane n][kk]
__device__ __align__(128) ull   g_Xp[(size_t)W_*N_*32]; // tf32-packed x rows [(w,n)][kk]
__device__ __align__(128) float g_bc[128];
__device__ __align__(128) float g_H  [TOT];       // h buffer (W,N,C)
__device__ __align__(128) float g_T  [TOT];       // transformed h
__device__ int   g_deg   [W_*N_];
__device__ int   g_rowptr[W_*N_];
__device__ int   g_cur   [W_*N_];
__device__ int   g_esrc  [W_*E_];
__device__ float g_ewt2  [W_*E_];

struct WPtrs {
    const float* sw[4]; const float* sb[4];
    const float* gw[4]; const float* gb[4];
};

// ---------------- helpers ----------------------------------------------------
__device__ __forceinline__ uint f2tf(float f) {
    uint u; asm("cvt.rna.tf32.f32 %0, %1;" : "=r"(u) : "f"(f)); return u;
}
__device__ __forceinline__ void mma_tf32(float (&c)[4], uint a0, uint a1, uint a2, uint a3,
                                         uint b0, uint b1) {
    asm volatile(
        "mma.sync.aligned.m16n8k8.row.col.f32.tf32.tf32.f32 "
        "{%0,%1,%2,%3}, {%4,%5,%6,%7}, {%8,%9}, {%0,%1,%2,%3};\n"
        : "+f"(c[0]), "+f"(c[1]), "+f"(c[2]), "+f"(c[3])
        : "r"(a0), "r"(a1), "r"(a2), "r"(a3), "r"(b0), "r"(b1));
}
__device__ __forceinline__ void cpasync16(void* sdst, const void* gsrc) {
    uint s = (uint)__cvta_generic_to_shared(sdst);
    asm volatile("cp.async.ca.shared.global [%0], [%1], 16;" :: "r"(s), "l"(gsrc));
}
__device__ __forceinline__ void cp_commit() { asm volatile("cp.async.commit_group;"); }
__device__ __forceinline__ void cp_wait0()  { asm volatile("cp.async.wait_group 0;"); }

// ---------------- K0: build packed weights + bias ----------------------------
__global__ void prep_kernel(WPtrs p) {
    int gid = blockIdx.x * blockDim.x + threadIdx.x;
    if (gid < 7*128*32) {
        int t   = gid >> 12;
        int rem = gid & 4095;
        int n   = rem >> 5;
        int kk  = rem & 31;
        int ks  = kk >> 2, q = kk & 3;
        int kw  = n >> 5, half = (n >> 4) & 1, ch = n & 15, k = 2*kw + 1;
        const float* src = half ? p.gw[kw] : p.sw[kw];
        int tt = t - 3 + kw;
        int c0 = 8*ks + q, c1 = c0 + 4;
        float v0 = 0.f, v1 = 0.f;
        if (tt >= 0 && tt < k) {
            v0 = src[(ch*64 + c0)*k + tt];
            v1 = src[(ch*64 + c1)*k + tt];
        }
        g_Wp[gid] = (ull)f2tf(v0) | ((ull)f2tf(v1) << 32);
    }
    if (gid < 128) {
        int j = gid;
        int kw = j >> 5; int half = (j >> 4) & 1; int ch = j & 15;
        g_bc[j] = half ? p.gb[kw][ch] : p.sb[kw][ch];
    }
}

// ---------------- K0b: pack x into tf32 A-fragment pairs ---------------------
__global__ void pack_x_kernel(const float4* __restrict__ x4) {
    int gid = blockIdx.x*256 + threadIdx.x;
    if (gid >= W_*N_*8) return;
    int row = gid >> 3, ks = gid & 7;
    float4 a = x4[(size_t)row*16 + ks*2];
    float4 b = x4[(size_t)row*16 + ks*2 + 1];
    ull* o = g_Xp + (size_t)row*32 + ks*4;
    o[0] = (ull)f2tf(a.x) | ((ull)f2tf(b.x) << 32);
    o[1] = (ull)f2tf(a.y) | ((ull)f2tf(b.y) << 32);
    o[2] = (ull)f2tf(a.z) | ((ull)f2tf(b.z) << 32);
    o[3] = (ull)f2tf(a.w) | ((ull)f2tf(b.w) << 32);
}

// ---------------- K1: inception via tf32 mma ---------------------------------
// Block: 16 nodes, 256 threads (8 warps). M = 12w x 16nodes, K=64, N=128.
// warp wid: mg = wid>>1 owns w in {3mg..3mg+2}; par = wid&1 owns ntiles nt=2u+par.
#define PAD 38
#define XS_ULL (18*16*PAD)
#define WS_ULL (128*PAD)
#define SMEM_BYTES ((XS_ULL + 2*WS_ULL)*8)

__global__ void __launch_bounds__(256) incep_mma_kernel() {
    extern __shared__ ull sm[];
    ull* Xs = sm;                 // [wi(18)][nloc(16)][PAD]
    ull* Ws = sm + XS_ULL;        // [2][n(128)][PAD]

    int tid = threadIdx.x;
    int n0  = blockIdx.x * 16;

    // zero-fill pad rows (wi = 0,1,2,15,16,17)
    {
        const int zl[6] = {0,1,2,15,16,17};
        for (int idx = tid; idx < 6*16*PAD; idx += 256) {
            int wi = zl[idx / (16*PAD)];
            Xs[wi*(16*PAD) + (idx % (16*PAD))] = 0ull;
        }
    }
    // fill valid rows via cp.async (12 w x 16 nodes x 16 chunks of 16B)
    for (int idx = tid; idx < 12*16*16; idx += 256) {
        int c = idx & 15, row = idx >> 4;
        int wrow = row >> 4, nloc = row & 15;
        cpasync16(&Xs[((wrow+3)*16 + nloc)*PAD + c*2],
                  g_Xp + ((size_t)(wrow*N_ + n0 + nloc)*32 + c*2));
    }
    // fill W stage 0
    for (int idx = tid; idx < 128*16; idx += 256) {
        int c = idx & 15, n = idx >> 4;
        cpasync16(&Ws[n*PAD + c*2], g_Wp + ((size_t)n*32 + c*2));
    }
    cp_commit();
    cp_wait0();
    __syncthreads();

    int lane = tid & 31, wid = tid >> 5;
    int mg = wid >> 1, par = wid & 1;
    int g = lane >> 2, q = lane & 3;

    float acc[3][8][4];
    #pragma unroll
    for (int j = 0; j < 3; j++)
        #pragma unroll
        for (int u = 0; u < 8; u++)
            #pragma unroll
            for (int c = 0; c < 4; c++) acc[j][u][c] = 0.f;

    for (int t = 0; t < 7; t++) {
        if (t < 6) {
            ull* Wn = Ws + ((t+1)&1)*WS_ULL;
            for (int idx = tid; idx < 128*16; idx += 256) {
                int c = idx & 15, n = idx >> 4;
                cpasync16(&Wn[n*PAD + c*2], g_Wp + ((size_t)((t+1)*128 + n)*32 + c*2));
            }
            cp_commit();
        }
        const ull* Wc = Ws + (t&1)*WS_ULL;
        int wibase = 3*mg + t;

        #pragma unroll
        for (int ks = 0; ks < 8; ks++) {
            uint a0[3], a1[3], a2[3], a3[3];
            #pragma unroll
            for (int j = 0; j < 3; j++) {
                ull v0 = Xs[((wibase+j)*16 + g    )*PAD + ks*4 + q];
                ull v1 = Xs[((wibase+j)*16 + g + 8)*PAD + ks*4 + q];
                a0[j] = (uint)v0; a2[j] = (uint)(v0 >> 32);
                a1[j] = (uint)v1; a3[j] = (uint)(v1 >> 32);
            }
            #pragma unroll
            for (int u = 0; u < 8; u++) {
                int nt = 2*u + par;
                int kw = nt >> 2;
                if (t >= 3-kw && t <= 3+kw) {
                    // B fragment: thread (g,q) holds B[q][nt*8+g], B[q+4][nt*8+g]
                    ull bw = Wc[(nt*8 + g)*PAD + ks*4 + q];
                    uint b0 = (uint)bw, b1 = (uint)(bw >> 32);
                    mma_tf32(acc[0][u], a0[0], a1[0], a2[0], a3[0], b0, b1);
                    mma_tf32(acc[1][u], a0[1], a1[1], a2[1], a3[1], b0, b1);
                    mma_tf32(acc[2][u], a0[2], a1[2], a2[2], a3[2], b0, b1);
                }
            }
        }
        if (t < 6) cp_wait0();
        __syncthreads();
    }

    // epilogue: bias + GLU, write g_H
    #pragma unroll
    for (int j = 0; j < 3; j++) {
        int w = 3*mg + j;
        #pragma unroll
        for (int us = 0; us < 8; us += 2) {
            int nts = 2*us + par;          // sig ntile; gate = nts+2 (u index us+1)
            float2 bs = *(const float2*)&g_bc[nts*8 + 2*q];
            float2 bg = *(const float2*)&g_bc[(nts+2)*8 + 2*q];
            float s0 = acc[j][us][0] + bs.x, s1 = acc[j][us][1] + bs.y;
            float s2 = acc[j][us][2] + bs.x, s3 = acc[j][us][3] + bs.y;
            float g0 = acc[j][us+1][0] + bg.x, g1 = acc[j][us+1][1] + bg.y;
            float g2 = acc[j][us+1][2] + bg.x, g3 = acc[j][us+1][3] + bg.y;
            float o0 = fmaxf(s0, 0.f) * (1.f/(1.f + __expf(-g0)));
            float o1 = fmaxf(s1, 0.f) * (1.f/(1.f + __expf(-g1)));
            float o2 = fmaxf(s2, 0.f) * (1.f/(1.f + __expf(-g2)));
            float o3 = fmaxf(s3, 0.f) * (1.f/(1.f + __expf(-g3)));
            int kw = nts >> 2;
            int cout = kw*16 + par*8 + 2*q;
            *(float2*)&g_H[((size_t)w*N_ + n0 + g    )*64 + cout] = make_float2(o0, o1);
            *(float2*)&g_H[((size_t)w*N_ + n0 + g + 8)*64 + cout] = make_float2(o2, o3);
        }
    }
}

// ---------------- K2: per-window dense transform T = H @ Wg ----------------
__global__ void __launch_bounds__(256) gemm_kernel(const float* __restrict__ gw, int hop) {
    __shared__ float4 Wsh[64*16];     // [cin][cout/4]
    int w = blockIdx.y;
    const float4* Wg = (const float4*)(gw + ((size_t)(hop*W_ + w))*64*64);
    for (int idx = threadIdx.x; idx < 1024; idx += 256) Wsh[idx] = Wg[idx];
    __syncthreads();

    int n  = blockIdx.x*128 + (threadIdx.x >> 1);
    int oh = threadIdx.x & 1;
    if (n >= N_) return;
    const float4* Hr = (const float4*)g_H + ((size_t)w*N_ + n)*16;
    float h[64];
    #pragma unroll
    for (int i4 = 0; i4 < 16; i4++) {
        float4 v = Hr[i4];
        h[i4*4+0]=v.x; h[i4*4+1]=v.y; h[i4*4+2]=v.z; h[i4*4+3]=v.w;
    }
    float4 acc[8];
    #pragma unroll
    for (int p = 0; p < 8; p++) acc[p] = make_float4(0.f,0.f,0.f,0.f);

    #pragma unroll 1
    for (int i = 0; i < 64; i++) {
        float hv = h[i];
        const float4* wr = &Wsh[i*16 + oh*8];
        #pragma unroll
        for (int p = 0; p < 8; p++) {
            float4 wv = wr[p];
            acc[p].x = fmaf(hv, wv.x, acc[p].x);
            acc[p].y = fmaf(hv, wv.y, acc[p].y);
            acc[p].z = fmaf(hv, wv.z, acc[p].z);
            acc[p].w = fmaf(hv, wv.w, acc[p].w);
        }
    }
    float4* Tr = (float4*)g_T + ((size_t)w*N_ + n)*16 + oh*8;
    #pragma unroll
    for (int p = 0; p < 8; p++) Tr[p] = acc[p];
}

// ---------------- CSR build (once) ------------------------------------------
__global__ void zerodeg_kernel() {
    int i = blockIdx.x*blockDim.x + threadIdx.x;
    if (i < W_*N_) g_deg[i] = 0;
}

__global__ void hist_kernel(const int* __restrict__ ei) {
    int g = blockIdx.x*blockDim.x + threadIdx.x;
    if (g >= W_*E_) return;
    int w = g / E_;
    int e = g - w*E_;
    int dst = ei[(size_t)(2*w+1)*E_ + e];
    atomicAdd(&g_deg[w*N_ + dst], 1);
}

__global__ void __launch_bounds__(512) scan_kernel() {
    __shared__ int wsum[16];
    int w = blockIdx.x;
    int t = threadIdx.x, lane = t & 31, wid = t >> 5;
    const int* deg = g_deg + w*N_;
    int base = t * 40;
    int s = 0;
    for (int k = 0; k < 40; k++) {
        int idx = base + k;
        if (idx < N_) s += deg[idx];
    }
    int v = s;
    #pragma unroll
    for (int d = 1; d < 32; d <<= 1) {
        int o = __shfl_up_sync(0xffffffffu, v, d);
        if (lane >= d) v += o;
    }
    if (lane == 31) wsum[wid] = v;
    __syncthreads();
    if (t == 0) {
        int r = 0;
        #pragma unroll
        for (int qq = 0; qq < 16; qq++) { int xq = wsum[qq]; wsum[qq] = r; r += xq; }
    }
    __syncthreads();
    int run = wsum[wid] + (v - s);
    for (int k = 0; k < 40; k++) {
        int idx = base + k;
        if (idx < N_) {
            int d = deg[idx];
            g_rowptr[w*N_ + idx] = run;
            g_cur   [w*N_ + idx] = run;
            run += d;
        }
    }
}

__global__ void place_kernel(const int* __restrict__ ei, const float* __restrict__ ewt) {
    int g = blockIdx.x*blockDim.x + threadIdx.x;
    if (g >= W_*E_) return;
    int w = g / E_;
    int e = g - w*E_;
    int src = ei[(size_t)(2*w)  *E_ + e];
    int dst = ei[(size_t)(2*w+1)*E_ + e];
    float wt = ewt[(size_t)w*E_ + e];
    int pos = atomicAdd(&g_cur[w*N_ + dst], 1);
    g_esrc[(size_t)w*E_ + pos] = src;
    g_ewt2[(size_t)w*E_ + pos] = wt;
}

// ---------------- K4: gather-aggregate + bias + ELU (+residual) -------------
__device__ __forceinline__ float elu1(float v) { return v > 0.f ? v : expm1f(v); }

__global__ void __launch_bounds__(256) agg_kernel(const float* __restrict__ gb, int hop,
                                                  const float* __restrict__ x,
                                                  float* __restrict__ out) {
    int g = blockIdx.x*256 + threadIdx.x;
    if (g >= W_*N_*4) return;
    int q  = g & 3;
    int wn = g >> 2;
    int w  = wn / N_;

    int beg = g_rowptr[wn];
    int end = beg + g_deg[wn];
    const int*    es = g_esrc + (size_t)w*E_;
    const float*  ep = g_ewt2 + (size_t)w*E_;
    const float4* Tb = (const float4*)g_T + (size_t)w*N_*16 + q*4;

    float4 a0 = make_float4(0,0,0,0), a1 = a0, a2 = a0, a3 = a0;
    #pragma unroll 2
    for (int e = beg; e < end; e++) {
        int   s  = es[e];
        float wt = ep[e];
        const float4* Ts = Tb + (size_t)s*16;
        float4 v0 = Ts[0], v1 = Ts[1], v2 = Ts[2], v3 = Ts[3];
        a0.x = fmaf(wt, v0.x, a0.x); a0.y = fmaf(wt, v0.y, a0.y);
        a0.z = fmaf(wt, v0.z, a0.z); a0.w = fmaf(wt, v0.w, a0.w);
        a1.x = fmaf(wt, v1.x, a1.x); a1.y = fmaf(wt, v1.y, a1.y);
        a1.z = fmaf(wt, v1.z, a1.z); a1.w = fmaf(wt, v1.w, a1.w);
        a2.x = fmaf(wt, v2.x, a2.x); a2.y = fmaf(wt, v2.y, a2.y);
        a2.z = fmaf(wt, v2.z, a2.z); a2.w = fmaf(wt, v2.w, a2.w);
        a3.x = fmaf(wt, v3.x, a3.x); a3.y = fmaf(wt, v3.y, a3.y);
        a3.z = fmaf(wt, v3.z, a3.z); a3.w = fmaf(wt, v3.w, a3.w);
    }

    const float4* bb = (const float4*)(gb + ((size_t)(hop*W_ + w))*64) + q*4;
    float4 b0 = bb[0], b1 = bb[1], b2 = bb[2], b3 = bb[3];
    a0.x = elu1(a0.x+b0.x); a0.y = elu1(a0.y+b0.y); a0.z = elu1(a0.z+b0.z); a0.w = elu1(a0.w+b0.w);
    a1.x = elu1(a1.x+b1.x); a1.y = elu1(a1.y+b1.y); a1.z = elu1(a1.z+b1.z); a1.w = elu1(a1.w+b1.w);
    a2.x = elu1(a2.x+b2.x); a2.y = elu1(a2.y+b2.y); a2.z = elu1(a2.z+b2.z); a2.w = elu1(a2.w+b2.w);
    a3.x = elu1(a3.x+b3.x); a3.y = elu1(a3.y+b3.y); a3.z = elu1(a3.z+b3.z); a3.w = elu1(a3.w+b3.w);

    size_t oi = (size_t)wn*16 + q*4;
    if (out) {
        const float4* xv = (const float4*)x + oi;
        float4 x0 = xv[0], x1 = xv[1], x2 = xv[2], x3 = xv[3];
        a0.x+=x0.x; a0.y+=x0.y; a0.z+=x0.z; a0.w+=x0.w;
        a1.x+=x1.x; a1.y+=x1.y; a1.z+=x1.z; a1.w+=x1.w;
        a2.x+=x2.x; a2.y+=x2.y; a2.z+=x2.z; a2.w+=x2.w;
        a3.x+=x3.x; a3.y+=x3.y; a3.z+=x3.z; a3.w+=x3.w;
        float4* o = (float4*)out + oi;
        o[0]=a0; o[1]=a1; o[2]=a2; o[3]=a3;
    } else {
        float4* o = (float4*)g_H + oi;
        o[0]=a0; o[1]=a1; o[2]=a2; o[3]=a3;
    }
}

// ---------------- launch -----------------------------------------------------
extern "C" void kernel_launch(void* const* d_in, const int* in_sizes, int n_in,
                              void* d_out, int out_size) {
    const float* x  = (const float*)d_in[0];
    const int*   ei = (const int*)  d_in[1];
    const float* ew = (const float*)d_in[2];

    WPtrs p;
    if (in_sizes[5] == 1024) {
        int idx = 3;
        for (int t = 0; t < 4; t++) {
            p.sw[t] = (const float*)d_in[idx++];
            p.sb[t] = (const float*)d_in[idx++];
            p.gw[t] = (const float*)d_in[idx++];
            p.gb[t] = (const float*)d_in[idx++];
        }
    } else {
        int idx = 3;
        for (int t = 0; t < 4; t++) {
            p.sw[t] = (const float*)d_in[idx++];
            p.sb[t] = (const float*)d_in[idx++];
        }
        for (int t = 0; t < 4; t++) {
            p.gw[t] = (const float*)d_in[idx++];
            p.gb[t] = (const float*)d_in[idx++];
        }
    }
    const float* gw = (const float*)d_in[19];
    const float* gb = (const float*)d_in[20];
    float* out = (float*)d_out;

    static bool attr_done = false;
    if (!attr_done) {
        cudaFuncSetAttribute(incep_mma_kernel,
                             cudaFuncAttributeMaxDynamicSharedMemorySize, SMEM_BYTES);
        attr_done = true;
    }

    prep_kernel<<<(7*128*32 + 255)/256, 256>>>(p);
    pack_x_kernel<<<(W_*N_*8 + 255)/256, 256>>>((const float4*)x);
    incep_mma_kernel<<<N_/16, 256, SMEM_BYTES>>>();

    zerodeg_kernel<<<(W_*N_ + 255)/256, 256>>>();
    hist_kernel<<<(W_*E_ + 255)/256, 256>>>(ei);
    scan_kernel<<<W_, 512>>>();
    place_kernel<<<(W_*E_ + 255)/256, 256>>>(ei, ew);

    for (int hop = 0; hop < 2; hop++) {
        gemm_kernel<<<dim3((N_ + 127)/128, W_), 256>>>(gw, hop);
        agg_kernel<<<(W_*N_*4 + 255)/256, 256>>>(gb, hop, x, hop == 1 ? out : nullptr);
    }
}

// round 5
// speedup vs baseline: 1.5620x; 1.1169x over previous
#include <cuda_runtime.h>
#include <cuda_fp16.h>
#include <cstdint>

#define W_ 12
#define N_ 20000
#define C_ 64
#define E_ 320000
#define TOT (W_*N_*C_)   // 15,360,000 floats
typedef unsigned long long ull;
typedef unsigned int uint;

// ---------------- scratch (device globals) ----------------------------------
// fp16-packed: ull at [row][ks*4+q] = {h2(k0,k0+1), h2(k0+8,k0+9)}, k0=ks*16+2q
__device__ __align__(128) ull   g_Wp[7*128*16];         // weights [t][lane n][16]
__device__ __align__(128) ull   g_Xp[(size_t)W_*N_*16]; // x rows  [(w,n)][16]
__device__ __align__(128) float g_bc[128];
__device__ __align__(128) float g_H  [TOT];       // h buffer (W,N,C)
__device__ __align__(128) float g_T  [TOT];       // transformed h
__device__ int   g_deg   [W_*N_];
__device__ int   g_rowptr[W_*N_];
__device__ int   g_cur   [W_*N_];
__device__ int   g_esrc  [W_*E_];
__device__ float g_ewt2  [W_*E_];

struct WPtrs {
    const float* sw[4]; const float* sb[4];
    const float* gw[4]; const float* gb[4];
};

// ---------------- helpers ----------------------------------------------------
__device__ __forceinline__ uint pack_h2(float a, float b) {
    __half2 h = __floats2half2_rn(a, b);
    return *(uint*)&h;
}
__device__ __forceinline__ void mma_f16(float (&c)[4], uint a0, uint a1, uint a2, uint a3,
                                        uint b0, uint b1) {
    asm volatile(
        "mma.sync.aligned.m16n8k16.row.col.f32.f16.f16.f32 "
        "{%0,%1,%2,%3}, {%4,%5,%6,%7}, {%8,%9}, {%0,%1,%2,%3};\n"
        : "+f"(c[0]), "+f"(c[1]), "+f"(c[2]), "+f"(c[3])
        : "r"(a0), "r"(a1), "r"(a2), "r"(a3), "r"(b0), "r"(b1));
}
__device__ __forceinline__ void cpasync16(void* sdst, const void* gsrc) {
    uint s = (uint)__cvta_generic_to_shared(sdst);
    asm volatile("cp.async.ca.shared.global [%0], [%1], 16;" :: "r"(s), "l"(gsrc));
}
__device__ __forceinline__ void cp_commit() { asm volatile("cp.async.commit_group;"); }
__device__ __forceinline__ void cp_wait0()  { asm volatile("cp.async.wait_group 0;"); }

// ---------------- K0: build packed weights + bias ----------------------------
__global__ void prep_kernel(WPtrs p) {
    int gid = blockIdx.x * blockDim.x + threadIdx.x;
    if (gid < 7*128*16) {
        int t   = gid >> 11;
        int rem = gid & 2047;
        int n   = rem >> 4;
        int idx = rem & 15;
        int ks  = idx >> 2, q = idx & 3;
        int kw  = n >> 5, half = (n >> 4) & 1, ch = n & 15, k = 2*kw + 1;
        const float* src = half ? p.gw[kw] : p.sw[kw];
        int tt = t - 3 + kw;
        int k0 = ks*16 + 2*q;
        float v0 = 0.f, v1 = 0.f, v2 = 0.f, v3 = 0.f;
        if (tt >= 0 && tt < k) {
            v0 = src[(ch*64 + k0    )*k + tt];
            v1 = src[(ch*64 + k0 + 1)*k + tt];
            v2 = src[(ch*64 + k0 + 8)*k + tt];
            v3 = src[(ch*64 + k0 + 9)*k + tt];
        }
        g_Wp[gid] = (ull)pack_h2(v0, v1) | ((ull)pack_h2(v2, v3) << 32);
    }
    if (gid < 128) {
        int j = gid;
        int kw = j >> 5; int half = (j >> 4) & 1; int ch = j & 15;
        g_bc[j] = half ? p.gb[kw][ch] : p.sb[kw][ch];
    }
}

// ---------------- K0b: pack x into fp16 A-fragment pairs ---------------------
__global__ void pack_x_kernel(const float* __restrict__ x) {
    int gid = blockIdx.x*256 + threadIdx.x;
    if (gid >= W_*N_*16) return;
    int row = gid >> 4, idx = gid & 15;
    int ks = idx >> 2, q = idx & 3;
    int k0 = ks*16 + 2*q;
    const float* xr = x + (size_t)row*64;
    float2 lo = *(const float2*)(xr + k0);
    float2 hi = *(const float2*)(xr + k0 + 8);
    g_Xp[gid] = (ull)pack_h2(lo.x, lo.y) | ((ull)pack_h2(hi.x, hi.y) << 32);
}

// ---------------- K1: inception via fp16 mma ---------------------------------
// Block: 16 nodes, 256 threads (8 warps). M = 12w x 16nodes, K=64, N=128.
// warp wid: mg = wid>>1 owns w in {3mg..3mg+2}; par = wid&1 owns ntiles nt=2u+par.
#define PAD 18
#define XS_ULL (18*16*PAD)
#define WS_ULL (128*PAD)
#define SMEM_BYTES ((XS_ULL + 2*WS_ULL)*8)

__global__ void __launch_bounds__(256) incep_mma_kernel() {
    extern __shared__ ull sm[];
    ull* Xs = sm;                 // [wi(18)][nloc(16)][PAD]
    ull* Ws = sm + XS_ULL;        // [2][n(128)][PAD]

    int tid = threadIdx.x;
    int n0  = blockIdx.x * 16;

    // zero-fill pad rows (wi = 0,1,2,15,16,17)
    {
        const int zl[6] = {0,1,2,15,16,17};
        for (int idx = tid; idx < 6*16*PAD; idx += 256) {
            int wi = zl[idx / (16*PAD)];
            Xs[wi*(16*PAD) + (idx % (16*PAD))] = 0ull;
        }
    }
    // fill valid rows via cp.async (12 w x 16 nodes x 8 chunks of 16B)
    for (int idx = tid; idx < 12*16*8; idx += 256) {
        int c = idx & 7, row = idx >> 3;
        int wrow = row >> 4, nloc = row & 15;
        cpasync16(&Xs[((wrow+3)*16 + nloc)*PAD + c*2],
                  g_Xp + ((size_t)(wrow*N_ + n0 + nloc)*16 + c*2));
    }
    // fill W stage 0
    for (int idx = tid; idx < 128*8; idx += 256) {
        int c = idx & 7, n = idx >> 3;
        cpasync16(&Ws[n*PAD + c*2], g_Wp + ((size_t)n*16 + c*2));
    }
    cp_commit();
    cp_wait0();
    __syncthreads();

    int lane = tid & 31, wid = tid >> 5;
    int mg = wid >> 1, par = wid & 1;
    int g = lane >> 2, q = lane & 3;

    float acc[3][8][4];
    #pragma unroll
    for (int j = 0; j < 3; j++)
        #pragma unroll
        for (int u = 0; u < 8; u++)
            #pragma unroll
            for (int c = 0; c < 4; c++) acc[j][u][c] = 0.f;

    for (int t = 0; t < 7; t++) {
        if (t < 6) {
            ull* Wn = Ws + ((t+1)&1)*WS_ULL;
            for (int idx = tid; idx < 128*8; idx += 256) {
                int c = idx & 7, n = idx >> 3;
                cpasync16(&Wn[n*PAD + c*2], g_Wp + ((size_t)((t+1)*128 + n)*16 + c*2));
            }
            cp_commit();
        }
        const ull* Wc = Ws + (t&1)*WS_ULL;
        int wibase = 3*mg + t;

        #pragma unroll
        for (int ks = 0; ks < 4; ks++) {
            uint a0[3], a1[3], a2[3], a3[3];
            #pragma unroll
            for (int j = 0; j < 3; j++) {
                ull v0 = Xs[((wibase+j)*16 + g    )*PAD + ks*4 + q];
                ull v1 = Xs[((wibase+j)*16 + g + 8)*PAD + ks*4 + q];
                a0[j] = (uint)v0; a2[j] = (uint)(v0 >> 32);
                a1[j] = (uint)v1; a3[j] = (uint)(v1 >> 32);
            }
            #pragma unroll
            for (int u = 0; u < 8; u++) {
                int nt = 2*u + par;
                int kw = nt >> 2;
                if (t >= 3-kw && t <= 3+kw) {
                    // B frag: thread (g,q) holds {B[2q],B[2q+1]},{B[2q+8],B[2q+9]} @ col nt*8+g
                    ull bw = Wc[(nt*8 + g)*PAD + ks*4 + q];
                    uint b0 = (uint)bw, b1 = (uint)(bw >> 32);
                    mma_f16(acc[0][u], a0[0], a1[0], a2[0], a3[0], b0, b1);
                    mma_f16(acc[1][u], a0[1], a1[1], a2[1], a3[1], b0, b1);
                    mma_f16(acc[2][u], a0[2], a1[2], a2[2], a3[2], b0, b1);
                }
            }
        }
        if (t < 6) cp_wait0();
        __syncthreads();
    }

    // epilogue: bias + GLU, write g_H
    #pragma unroll
    for (int j = 0; j < 3; j++) {
        int w = 3*mg + j;
        #pragma unroll
        for (int us = 0; us < 8; us += 2) {
            int nts = 2*us + par;          // sig ntile; gate = nts+2 (u index us+1)
            float2 bs = *(const float2*)&g_bc[nts*8 + 2*q];
            float2 bg = *(const float2*)&g_bc[(nts+2)*8 + 2*q];
            float s0 = acc[j][us][0] + bs.x, s1 = acc[j][us][1] + bs.y;
            float s2 = acc[j][us][2] + bs.x, s3 = acc[j][us][3] + bs.y;
            float g0 = acc[j][us+1][0] + bg.x, g1 = acc[j][us+1][1] + bg.y;
            float g2 = acc[j][us+1][2] + bg.x, g3 = acc[j][us+1][3] + bg.y;
            float o0 = fmaxf(s0, 0.f) * (1.f/(1.f + __expf(-g0)));
            float o1 = fmaxf(s1, 0.f) * (1.f/(1.f + __expf(-g1)));
            float o2 = fmaxf(s2, 0.f) * (1.f/(1.f + __expf(-g2)));
            float o3 = fmaxf(s3, 0.f) * (1.f/(1.f + __expf(-g3)));
            int kw = nts >> 2;
            int cout = kw*16 + par*8 + 2*q;
            *(float2*)&g_H[((size_t)w*N_ + n0 + g    )*64 + cout] = make_float2(o0, o1);
            *(float2*)&g_H[((size_t)w*N_ + n0 + g + 8)*64 + cout] = make_float2(o2, o3);
        }
    }
}

// ---------------- K2: per-window dense transform T = H @ Wg ----------------
__global__ void __launch_bounds__(256) gemm_kernel(const float* __restrict__ gw, int hop) {
    __shared__ float4 Wsh[64*16];     // [cin][cout/4]
    int w = blockIdx.y;
    const float4* Wg = (const float4*)(gw + ((size_t)(hop*W_ + w))*64*64);
    for (int idx = threadIdx.x; idx < 1024; idx += 256) Wsh[idx] = Wg[idx];
    __syncthreads();

    int n  = blockIdx.x*128 + (threadIdx.x >> 1);
    int oh = threadIdx.x & 1;
    if (n >= N_) return;
    const float4* Hr = (const float4*)g_H + ((size_t)w*N_ + n)*16;
    float h[64];
    #pragma unroll
    for (int i4 = 0; i4 < 16; i4++) {
        float4 v = Hr[i4];
        h[i4*4+0]=v.x; h[i4*4+1]=v.y; h[i4*4+2]=v.z; h[i4*4+3]=v.w;
    }
    float4 acc[8];
    #pragma unroll
    for (int p = 0; p < 8; p++) acc[p] = make_float4(0.f,0.f,0.f,0.f);

    #pragma unroll 1
    for (int i = 0; i < 64; i++) {
        float hv = h[i];
        const float4* wr = &Wsh[i*16 + oh*8];
        #pragma unroll
        for (int p = 0; p < 8; p++) {
            float4 wv = wr[p];
            acc[p].x = fmaf(hv, wv.x, acc[p].x);
            acc[p].y = fmaf(hv, wv.y, acc[p].y);
            acc[p].z = fmaf(hv, wv.z, acc[p].z);
            acc[p].w = fmaf(hv, wv.w, acc[p].w);
        }
    }
    float4* Tr = (float4*)g_T + ((size_t)w*N_ + n)*16 + oh*8;
    #pragma unroll
    for (int p = 0; p < 8; p++) Tr[p] = acc[p];
}

// ---------------- CSR build (once) ------------------------------------------
__global__ void zerodeg_kernel() {
    int i = blockIdx.x*blockDim.x + threadIdx.x;
    if (i < W_*N_) g_deg[i] = 0;
}

__global__ void hist_kernel(const int* __restrict__ ei) {
    int g = blockIdx.x*blockDim.x + threadIdx.x;
    if (g >= W_*E_) return;
    int w = g / E_;
    int e = g - w*E_;
    int dst = ei[(size_t)(2*w+1)*E_ + e];
    atomicAdd(&g_deg[w*N_ + dst], 1);
}

__global__ void __launch_bounds__(512) scan_kernel() {
    __shared__ int wsum[16];
    int w = blockIdx.x;
    int t = threadIdx.x, lane = t & 31, wid = t >> 5;
    const int* deg = g_deg + w*N_;
    int base = t * 40;
    int s = 0;
    for (int k = 0; k < 40; k++) {
        int idx = base + k;
        if (idx < N_) s += deg[idx];
    }
    int v = s;
    #pragma unroll
    for (int d = 1; d < 32; d <<= 1) {
        int o = __shfl_up_sync(0xffffffffu, v, d);
        if (lane >= d) v += o;
    }
    if (lane == 31) wsum[wid] = v;
    __syncthreads();
    if (t == 0) {
        int r = 0;
        #pragma unroll
        for (int qq = 0; qq < 16; qq++) { int xq = wsum[qq]; wsum[qq] = r; r += xq; }
    }
    __syncthreads();
    int run = wsum[wid] + (v - s);
    for (int k = 0; k < 40; k++) {
        int idx = base + k;
        if (idx < N_) {
            int d = deg[idx];
            g_rowptr[w*N_ + idx] = run;
            g_cur   [w*N_ + idx] = run;
            run += d;
        }
    }
}

__global__ void place_kernel(const int* __restrict__ ei, const float* __restrict__ ewt) {
    int g = blockIdx.x*blockDim.x + threadIdx.x;
    if (g >= W_*E_) return;
    int w = g / E_;
    int e = g - w*E_;
    int src = ei[(size_t)(2*w)  *E_ + e];
    int dst = ei[(size_t)(2*w+1)*E_ + e];
    float wt = ewt[(size_t)w*E_ + e];
    int pos = atomicAdd(&g_cur[w*N_ + dst], 1);
    g_esrc[(size_t)w*E_ + pos] = src;
    g_ewt2[(size_t)w*E_ + pos] = wt;
}

// ---------------- K4: gather-aggregate + bias + ELU (+residual) -------------
__device__ __forceinline__ float elu1(float v) { return v > 0.f ? v : expm1f(v); }

__global__ void __launch_bounds__(256) agg_kernel(const float* __restrict__ gb, int hop,
                                                  const float* __restrict__ x,
                                                  float* __restrict__ out) {
    int g = blockIdx.x*256 + threadIdx.x;
    if (g >= W_*N_*4) return;
    int q  = g & 3;
    int wn = g >> 2;
    int w  = wn / N_;

    int beg = g_rowptr[wn];
    int end = beg + g_deg[wn];
    const int*    es = g_esrc + (size_t)w*E_;
    const float*  ep = g_ewt2 + (size_t)w*E_;
    const float4* Tb = (const float4*)g_T + (size_t)w*N_*16 + q*4;

    float4 a0 = make_float4(0,0,0,0), a1 = a0, a2 = a0, a3 = a0;
    #pragma unroll 2
    for (int e = beg; e < end; e++) {
        int   s  = es[e];
        float wt = ep[e];
        const float4* Ts = Tb + (size_t)s*16;
        float4 v0 = Ts[0], v1 = Ts[1], v2 = Ts[2], v3 = Ts[3];
        a0.x = fmaf(wt, v0.x, a0.x); a0.y = fmaf(wt, v0.y, a0.y);
        a0.z = fmaf(wt, v0.z, a0.z); a0.w = fmaf(wt, v0.w, a0.w);
        a1.x = fmaf(wt, v1.x, a1.x); a1.y = fmaf(wt, v1.y, a1.y);
        a1.z = fmaf(wt, v1.z, a1.z); a1.w = fmaf(wt, v1.w, a1.w);
        a2.x = fmaf(wt, v2.x, a2.x); a2.y = fmaf(wt, v2.y, a2.y);
        a2.z = fmaf(wt, v2.z, a2.z); a2.w = fmaf(wt, v2.w, a2.w);
        a3.x = fmaf(wt, v3.x, a3.x); a3.y = fmaf(wt, v3.y, a3.y);
        a3.z = fmaf(wt, v3.z, a3.z); a3.w = fmaf(wt, v3.w, a3.w);
    }

    const float4* bb = (const float4*)(gb + ((size_t)(hop*W_ + w))*64) + q*4;
    float4 b0 = bb[0], b1 = bb[1], b2 = bb[2], b3 = bb[3];
    a0.x = elu1(a0.x+b0.x); a0.y = elu1(a0.y+b0.y); a0.z = elu1(a0.z+b0.z); a0.w = elu1(a0.w+b0.w);
    a1.x = elu1(a1.x+b1.x); a1.y = elu1(a1.y+b1.y); a1.z = elu1(a1.z+b1.z); a1.w = elu1(a1.w+b1.w);
    a2.x = elu1(a2.x+b2.x); a2.y = elu1(a2.y+b2.y); a2.z = elu1(a2.z+b2.z); a2.w = elu1(a2.w+b2.w);
    a3.x = elu1(a3.x+b3.x); a3.y = elu1(a3.y+b3.y); a3.z = elu1(a3.z+b3.z); a3.w = elu1(a3.w+b3.w);

    size_t oi = (size_t)wn*16 + q*4;
    if (out) {
        const float4* xv = (const float4*)x + oi;
        float4 x0 = xv[0], x1 = xv[1], x2 = xv[2], x3 = xv[3];
        a0.x+=x0.x; a0.y+=x0.y; a0.z+=x0.z; a0.w+=x0.w;
        a1.x+=x1.x; a1.y+=x1.y; a1.z+=x1.z; a1.w+=x1.w;
        a2.x+=x2.x; a2.y+=x2.y; a2.z+=x2.z; a2.w+=x2.w;
        a3.x+=x3.x; a3.y+=x3.y; a3.z+=x3.z; a3.w+=x3.w;
        float4* o = (float4*)out + oi;
        o[0]=a0; o[1]=a1; o[2]=a2; o[3]=a3;
    } else {
        float4* o = (float4*)g_H + oi;
        o[0]=a0; o[1]=a1; o[2]=a2; o[3]=a3;
    }
}

// ---------------- launch -----------------------------------------------------
extern "C" void kernel_launch(void* const* d_in, const int* in_sizes, int n_in,
                              void* d_out, int out_size) {
    const float* x  = (const float*)d_in[0];
    const int*   ei = (const int*)  d_in[1];
    const float* ew = (const float*)d_in[2];

    WPtrs p;
    if (in_sizes[5] == 1024) {
        int idx = 3;
        for (int t = 0; t < 4; t++) {
            p.sw[t] = (const float*)d_in[idx++];
            p.sb[t] = (const float*)d_in[idx++];
            p.gw[t] = (const float*)d_in[idx++];
            p.gb[t] = (const float*)d_in[idx++];
        }
    } else {
        int idx = 3;
        for (int t = 0; t < 4; t++) {
            p.sw[t] = (const float*)d_in[idx++];
            p.sb[t] = (const float*)d_in[idx++];
        }
        for (int t = 0; t < 4; t++) {
            p.gw[t] = (const float*)d_in[idx++];
            p.gb[t] = (const float*)d_in[idx++];
        }
    }
    const float* gw = (const float*)d_in[19];
    const float* gb = (const float*)d_in[20];
    float* out = (float*)d_out;

    static bool attr_done = false;
    if (!attr_done) {
        cudaFuncSetAttribute(incep_mma_kernel,
                             cudaFuncAttributeMaxDynamicSharedMemorySize, SMEM_BYTES);
        attr_done = true;
    }

    prep_kernel<<<(7*128*16 + 255)/256, 256>>>(p);
    pack_x_kernel<<<(W_*N_*16 + 255)/256, 256>>>(x);
    incep_mma_kernel<<<N_/16, 256, SMEM_BYTES>>>();

    zerodeg_kernel<<<(W_*N_ + 255)/256, 256>>>();
    hist_kernel<<<(W_*E_ + 255)/256, 256>>>(ei);
    scan_kernel<<<W_, 512>>>();
    place_kernel<<<(W_*E_ + 255)/256, 256>>>(ei, ew);

    for (int hop = 0; hop < 2; hop++) {
        gemm_kernel<<<dim3((N_ + 127)/128, W_), 256>>>(gw, hop);
        agg_kernel<<<(W_*N_*4 + 255)/256, 256>>>(gb, hop, x, hop == 1 ? out : nullptr);
    }
}

// round 7
// speedup vs baseline: 1.8590x; 1.1901x over previous
#include <cuda_runtime.h>
#include <cuda_fp16.h>
#include <cstdint>

#define W_ 12
#define N_ 20000
#define C_ 64
#define E_ 320000
#define TOT (W_*N_*C_)   // 15,360,000
typedef unsigned long long ull;
typedef unsigned int uint;

// ---------------- scratch (device globals) ----------------------------------
// fp16-packed: ull at [row][ks*4+q] = {h2(k0,k0+1), h2(k0+8,k0+9)}, k0=ks*16+2q
__device__ __align__(128) ull    g_Wp[7*128*16];         // weights [t][lane n][16]
__device__ __align__(128) ull    g_Xp[(size_t)W_*N_*16]; // x rows  [(w,n)][16]
__device__ __align__(128) float  g_bc[128];
__device__ __align__(128) __half g_Hh [TOT];      // h buffer, fp16 (W,N,C)
__device__ __align__(128) float  g_Agg[TOT];      // aggregated raw h (fp32)
__device__ int  g_deg   [W_*N_];
__device__ int  g_rowptr[W_*N_];
__device__ int  g_cur   [W_*N_];
__device__ int2 g_edge  [W_*E_];   // {src, wt bits}

struct WPtrs {
    const float* sw[4]; const float* sb[4];
    const float* gw[4]; const float* gb[4];
};

// ---------------- helpers ----------------------------------------------------
__device__ __forceinline__ uint pack_h2(float a, float b) {
    __half2 h = __floats2half2_rn(a, b);
    return *(uint*)&h;
}
__device__ __forceinline__ void mma_f16(float (&c)[4], uint a0, uint a1, uint a2, uint a3,
                                        uint b0, uint b1) {
    asm volatile(
        "mma.sync.aligned.m16n8k16.row.col.f32.f16.f16.f32 "
        "{%0,%1,%2,%3}, {%4,%5,%6,%7}, {%8,%9}, {%0,%1,%2,%3};\n"
        : "+f"(c[0]), "+f"(c[1]), "+f"(c[2]), "+f"(c[3])
        : "r"(a0), "r"(a1), "r"(a2), "r"(a3), "r"(b0), "r"(b1));
}
__device__ __forceinline__ void cpasync16(void* sdst, const void* gsrc) {
    uint s = (uint)__cvta_generic_to_shared(sdst);
    asm volatile("cp.async.ca.shared.global [%0], [%1], 16;" :: "r"(s), "l"(gsrc));
}
__device__ __forceinline__ void cp_commit() { asm volatile("cp.async.commit_group;"); }
__device__ __forceinline__ void cp_wait0()  { asm volatile("cp.async.wait_group 0;"); }

// ---------------- K0: build packed weights + bias ----------------------------
__global__ void prep_kernel(WPtrs p) {
    int gid = blockIdx.x * blockDim.x + threadIdx.x;
    if (gid < 7*128*16) {
        int t   = gid >> 11;
        int rem = gid & 2047;
        int n   = rem >> 4;
        int idx = rem & 15;
        int ks  = idx >> 2, q = idx & 3;
        int kw  = n >> 5, half = (n >> 4) & 1, ch = n & 15, k = 2*kw + 1;
        const float* src = half ? p.gw[kw] : p.sw[kw];
        int tt = t - 3 + kw;
        int k0 = ks*16 + 2*q;
        float v0 = 0.f, v1 = 0.f, v2 = 0.f, v3 = 0.f;
        if (tt >= 0 && tt < k) {
            v0 = src[(ch*64 + k0    )*k + tt];
            v1 = src[(ch*64 + k0 + 1)*k + tt];
            v2 = src[(ch*64 + k0 + 8)*k + tt];
            v3 = src[(ch*64 + k0 + 9)*k + tt];
        }
        g_Wp[gid] = (ull)pack_h2(v0, v1) | ((ull)pack_h2(v2, v3) << 32);
    }
    if (gid < 128) {
        int j = gid;
        int kw = j >> 5; int half = (j >> 4) & 1; int ch = j & 15;
        g_bc[j] = half ? p.gb[kw][ch] : p.sb[kw][ch];
    }
}

// ---------------- K0b: pack x into fp16 A-fragment pairs ---------------------
__global__ void pack_x_kernel(const float* __restrict__ x) {
    int gid = blockIdx.x*256 + threadIdx.x;
    if (gid >= W_*N_*16) return;
    int row = gid >> 4, idx = gid & 15;
    int ks = idx >> 2, q = idx & 3;
    int k0 = ks*16 + 2*q;
    const float* xr = x + (size_t)row*64;
    float2 lo = *(const float2*)(xr + k0);
    float2 hi = *(const float2*)(xr + k0 + 8);
    g_Xp[gid] = (ull)pack_h2(lo.x, lo.y) | ((ull)pack_h2(hi.x, hi.y) << 32);
}

// ---------------- K1: inception via fp16 mma ---------------------------------
#define PAD 18
#define XS_ULL (18*16*PAD)
#define WS_ULL (128*PAD)
#define SMEM_BYTES ((XS_ULL + 2*WS_ULL)*8)

__global__ void __launch_bounds__(256) incep_mma_kernel() {
    extern __shared__ ull sm[];
    ull* Xs = sm;                 // [wi(18)][nloc(16)][PAD]
    ull* Ws = sm + XS_ULL;        // [2][n(128)][PAD]

    int tid = threadIdx.x;
    int n0  = blockIdx.x * 16;

    {
        const int zl[6] = {0,1,2,15,16,17};
        for (int idx = tid; idx < 6*16*PAD; idx += 256) {
            int wi = zl[idx / (16*PAD)];
            Xs[wi*(16*PAD) + (idx % (16*PAD))] = 0ull;
        }
    }
    for (int idx = tid; idx < 12*16*8; idx += 256) {
        int c = idx & 7, row = idx >> 3;
        int wrow = row >> 4, nloc = row & 15;
        cpasync16(&Xs[((wrow+3)*16 + nloc)*PAD + c*2],
                  g_Xp + ((size_t)(wrow*N_ + n0 + nloc)*16 + c*2));
    }
    for (int idx = tid; idx < 128*8; idx += 256) {
        int c = idx & 7, n = idx >> 3;
        cpasync16(&Ws[n*PAD + c*2], g_Wp + ((size_t)n*16 + c*2));
    }
    cp_commit();
    cp_wait0();
    __syncthreads();

    int lane = tid & 31, wid = tid >> 5;
    int mg = wid >> 1, par = wid & 1;
    int g = lane >> 2, q = lane & 3;

    float acc[3][8][4];
    #pragma unroll
    for (int j = 0; j < 3; j++)
        #pragma unroll
        for (int u = 0; u < 8; u++)
            #pragma unroll
            for (int c = 0; c < 4; c++) acc[j][u][c] = 0.f;

    for (int t = 0; t < 7; t++) {
        if (t < 6) {
            ull* Wn = Ws + ((t+1)&1)*WS_ULL;
            for (int idx = tid; idx < 128*8; idx += 256) {
                int c = idx & 7, n = idx >> 3;
                cpasync16(&Wn[n*PAD + c*2], g_Wp + ((size_t)((t+1)*128 + n)*16 + c*2));
            }
            cp_commit();
        }
        const ull* Wc = Ws + (t&1)*WS_ULL;
        int wibase = 3*mg + t;

        #pragma unroll
        for (int ks = 0; ks < 4; ks++) {
            uint a0[3], a1[3], a2[3], a3[3];
            #pragma unroll
            for (int j = 0; j < 3; j++) {
                ull v0 = Xs[((wibase+j)*16 + g    )*PAD + ks*4 + q];
                ull v1 = Xs[((wibase+j)*16 + g + 8)*PAD + ks*4 + q];
                a0[j] = (uint)v0; a2[j] = (uint)(v0 >> 32);
                a1[j] = (uint)v1; a3[j] = (uint)(v1 >> 32);
            }
            #pragma unroll
            for (int u = 0; u < 8; u++) {
                int nt = 2*u + par;
                int kw = nt >> 2;
                if (t >= 3-kw && t <= 3+kw) {
                    ull bw = Wc[(nt*8 + g)*PAD + ks*4 + q];
                    uint b0 = (uint)bw, b1 = (uint)(bw >> 32);
                    mma_f16(acc[0][u], a0[0], a1[0], a2[0], a3[0], b0, b1);
                    mma_f16(acc[1][u], a0[1], a1[1], a2[1], a3[1], b0, b1);
                    mma_f16(acc[2][u], a0[2], a1[2], a2[2], a3[2], b0, b1);
                }
            }
        }
        if (t < 6) cp_wait0();
        __syncthreads();
    }

    // epilogue: bias + GLU, write g_Hh (fp16)
    #pragma unroll
    for (int j = 0; j < 3; j++) {
        int w = 3*mg + j;
        #pragma unroll
        for (int us = 0; us < 8; us += 2) {
            int nts = 2*us + par;
            float2 bs = *(const float2*)&g_bc[nts*8 + 2*q];
            float2 bg = *(const float2*)&g_bc[(nts+2)*8 + 2*q];
            float s0 = acc[j][us][0] + bs.x, s1 = acc[j][us][1] + bs.y;
            float s2 = acc[j][us][2] + bs.x, s3 = acc[j][us][3] + bs.y;
            float g0 = acc[j][us+1][0] + bg.x, g1 = acc[j][us+1][1] + bg.y;
            float g2 = acc[j][us+1][2] + bg.x, g3 = acc[j][us+1][3] + bg.y;
            float o0 = fmaxf(s0, 0.f) * (1.f/(1.f + __expf(-g0)));
            float o1 = fmaxf(s1, 0.f) * (1.f/(1.f + __expf(-g1)));
            float o2 = fmaxf(s2, 0.f) * (1.f/(1.f + __expf(-g2)));
            float o3 = fmaxf(s3, 0.f) * (1.f/(1.f + __expf(-g3)));
            int kw = nts >> 2;
            int cout = kw*16 + par*8 + 2*q;
            *(__half2*)&g_Hh[((size_t)w*N_ + n0 + g    )*64 + cout] = __floats2half2_rn(o0, o1);
            *(__half2*)&g_Hh[((size_t)w*N_ + n0 + g + 8)*64 + cout] = __floats2half2_rn(o2, o3);
        }
    }
}

// ---------------- CSR build (once) ------------------------------------------
__global__ void zerodeg_kernel() {
    int i = blockIdx.x*blockDim.x + threadIdx.x;
    if (i < W_*N_) g_deg[i] = 0;
}

__global__ void hist_kernel(const int* __restrict__ ei) {
    int g = blockIdx.x*blockDim.x + threadIdx.x;
    if (g >= W_*E_) return;
    int w = g / E_;
    int e = g - w*E_;
    int dst = ei[(size_t)(2*w+1)*E_ + e];
    atomicAdd(&g_deg[w*N_ + dst], 1);
}

__global__ void __launch_bounds__(512) scan_kernel() {
    __shared__ int wsum[16];
    int w = blockIdx.x;
    int t = threadIdx.x, lane = t & 31, wid = t >> 5;
    const int* deg = g_deg + w*N_;
    int base = t * 40;
    int s = 0;
    for (int k = 0; k < 40; k++) {
        int idx = base + k;
        if (idx < N_) s += deg[idx];
    }
    int v = s;
    #pragma unroll
    for (int d = 1; d < 32; d <<= 1) {
        int o = __shfl_up_sync(0xffffffffu, v, d);
        if (lane >= d) v += o;
    }
    if (lane == 31) wsum[wid] = v;
    __syncthreads();
    if (t == 0) {
        int r = 0;
        #pragma unroll
        for (int qq = 0; qq < 16; qq++) { int xq = wsum[qq]; wsum[qq] = r; r += xq; }
    }
    __syncthreads();
    int run = wsum[wid] + (v - s);
    for (int k = 0; k < 40; k++) {
        int idx = base + k;
        if (idx < N_) {
            int d = deg[idx];
            g_rowptr[w*N_ + idx] = run;
            g_cur   [w*N_ + idx] = run;
            run += d;
        }
    }
}

__global__ void place_kernel(const int* __restrict__ ei, const float* __restrict__ ewt) {
    int g = blockIdx.x*blockDim.x + threadIdx.x;
    if (g >= W_*E_) return;
    int w = g / E_;
    int e = g - w*E_;
    int src = ei[(size_t)(2*w)  *E_ + e];
    int dst = ei[(size_t)(2*w+1)*E_ + e];
    float wt = ewt[(size_t)w*E_ + e];
    int pos = atomicAdd(&g_cur[w*N_ + dst], 1);
    g_edge[(size_t)w*E_ + pos] = make_int2(src, __float_as_int(wt));
}

// ---------------- K4: gather-aggregate raw h (fp16 rows) ---------------------
__global__ void __launch_bounds__(256) agg_kernel() {
    int g = blockIdx.x*256 + threadIdx.x;
    if (g >= W_*N_*8) return;
    int q  = g & 7;           // 8-channel slice
    int wn = g >> 3;
    int w  = wn / N_;

    int beg = g_rowptr[wn];
    int end = beg + g_deg[wn];
    const int2*  ed = g_edge + (size_t)w*E_;
    const uint4* Hb = (const uint4*)g_Hh + (size_t)w*N_*8 + q;

    float a0=0.f,a1=0.f,a2=0.f,a3=0.f,a4=0.f,a5=0.f,a6=0.f,a7=0.f;
    #pragma unroll 2
    for (int e = beg; e < end; e++) {
        int2 pr = ed[e];
        float wt = __int_as_float(pr.y);
        uint4 v = Hb[(size_t)pr.x*8];
        const __half2* hp = (const __half2*)&v;
        float2 f0 = __half22float2(hp[0]);
        float2 f1 = __half22float2(hp[1]);
        float2 f2 = __half22float2(hp[2]);
        float2 f3 = __half22float2(hp[3]);
        a0 = fmaf(wt, f0.x, a0); a1 = fmaf(wt, f0.y, a1);
        a2 = fmaf(wt, f1.x, a2); a3 = fmaf(wt, f1.y, a3);
        a4 = fmaf(wt, f2.x, a4); a5 = fmaf(wt, f2.y, a5);
        a6 = fmaf(wt, f3.x, a6); a7 = fmaf(wt, f3.y, a7);
    }
    float4* o = (float4*)g_Agg + (size_t)wn*16 + q*2;
    o[0] = make_float4(a0,a1,a2,a3);
    o[1] = make_float4(a4,a5,a6,a7);
}

// ---------------- K5: gemm on aggregate + bias + ELU (+residual) ------------
__device__ __forceinline__ float elu1(float v) { return v > 0.f ? v : expm1f(v); }

__global__ void __launch_bounds__(256) gemmelu_kernel(const float* __restrict__ gw,
                                                      const float* __restrict__ gb, int hop,
                                                      const float* __restrict__ x,
                                                      float* __restrict__ out) {
    __shared__ float4 Wsh[64*16];     // [cin][cout/4]
    int w = blockIdx.y;
    const float4* Wg = (const float4*)(gw + ((size_t)(hop*W_ + w))*64*64);
    for (int idx = threadIdx.x; idx < 1024; idx += 256) Wsh[idx] = Wg[idx];
    __syncthreads();

    int n  = blockIdx.x*128 + (threadIdx.x >> 1);
    int oh = threadIdx.x & 1;
    if (n >= N_) return;
    const float4* Ar = (const float4*)g_Agg + ((size_t)w*N_ + n)*16;
    float h[64];
    #pragma unroll
    for (int i4 = 0; i4 < 16; i4++) {
        float4 v = Ar[i4];
        h[i4*4+0]=v.x; h[i4*4+1]=v.y; h[i4*4+2]=v.z; h[i4*4+3]=v.w;
    }
    float4 acc[8];
    const float4* bb = (const float4*)(gb + ((size_t)(hop*W_ + w))*64) + oh*8;
    #pragma unroll
    for (int p = 0; p < 8; p++) acc[p] = bb[p];

    #pragma unroll 1
    for (int i = 0; i < 64; i++) {
        float hv = h[i];
        const float4* wr = &Wsh[i*16 + oh*8];
        #pragma unroll
        for (int p = 0; p < 8; p++) {
            float4 wv = wr[p];
            acc[p].x = fmaf(hv, wv.x, acc[p].x);
            acc[p].y = fmaf(hv, wv.y, acc[p].y);
            acc[p].z = fmaf(hv, wv.z, acc[p].z);
            acc[p].w = fmaf(hv, wv.w, acc[p].w);
        }
    }
    #pragma unroll
    for (int p = 0; p < 8; p++) {
        acc[p].x = elu1(acc[p].x); acc[p].y = elu1(acc[p].y);
        acc[p].z = elu1(acc[p].z); acc[p].w = elu1(acc[p].w);
    }

    if (out) {
        size_t oi = ((size_t)w*N_ + n)*16 + oh*8;
        const float4* xv = (const float4*)x + oi;
        float4* o = (float4*)out + oi;
        #pragma unroll
        for (int p = 0; p < 8; p++) {
            float4 xw = xv[p];
            o[p] = make_float4(acc[p].x+xw.x, acc[p].y+xw.y, acc[p].z+xw.z, acc[p].w+xw.w);
        }
    } else {
        // 32 couts per thread = 32 floats = 16 half2 = 16 uints = 4 uint4
        uint4 pk[4];
        uint* pu = (uint*)pk;
        #pragma unroll
        for (int p = 0; p < 8; p++) {
            pu[p*2  ] = pack_h2(acc[p].x, acc[p].y);
            pu[p*2+1] = pack_h2(acc[p].z, acc[p].w);
        }
        uint4* o = (uint4*)(g_Hh + ((size_t)w*N_ + n)*64 + oh*32);
        o[0] = pk[0]; o[1] = pk[1]; o[2] = pk[2]; o[3] = pk[3];
    }
}

// ---------------- launch -----------------------------------------------------
extern "C" void kernel_launch(void* const* d_in, const int* in_sizes, int n_in,
                              void* d_out, int out_size) {
    const float* x  = (const float*)d_in[0];
    const int*   ei = (const int*)  d_in[1];
    const float* ew = (const float*)d_in[2];

    WPtrs p;
    if (in_sizes[5] == 1024) {
        int idx = 3;
        for (int t = 0; t < 4; t++) {
            p.sw[t] = (const float*)d_in[idx++];
            p.sb[t] = (const float*)d_in[idx++];
            p.gw[t] = (const float*)d_in[idx++];
            p.gb[t] = (const float*)d_in[idx++];
        }
    } else {
        int idx = 3;
        for (int t = 0; t < 4; t++) {
            p.sw[t] = (const float*)d_in[idx++];
            p.sb[t] = (const float*)d_in[idx++];
        }
        for (int t = 0; t < 4; t++) {
            p.gw[t] = (const float*)d_in[idx++];
            p.gb[t] = (const float*)d_in[idx++];
        }
    }
    const float* gw = (const float*)d_in[19];
    const float* gb = (const float*)d_in[20];
    float* out = (float*)d_out;

    static bool attr_done = false;
    if (!attr_done) {
        cudaFuncSetAttribute(incep_mma_kernel,
                             cudaFuncAttributeMaxDynamicSharedMemorySize, SMEM_BYTES);
        attr_done = true;
    }

    prep_kernel<<<(7*128*16 + 255)/256, 256>>>(p);
    pack_x_kernel<<<(W_*N_*16 + 255)/256, 256>>>(x);
    incep_mma_kernel<<<N_/16, 256, SMEM_BYTES>>>();

    zerodeg_kernel<<<(W_*N_ + 255)/256, 256>>>();
    hist_kernel<<<(W_*E_ + 255)/256, 256>>>(ei);
    scan_kernel<<<W_, 512>>>();
    place_kernel<<<(W_*E_ + 255)/256, 256>>>(ei, ew);

    for (int hop = 0; hop < 2; hop++) {
        agg_kernel<<<(W_*N_*8 + 255)/256, 256>>>();
        gemmelu_kernel<<<dim3((N_ + 127)/128, W_), 256>>>(gw, gb, hop, x,
                                                          hop == 1 ? out : nullptr);
    }
}

// round 8
// speedup vs baseline: 2.5741x; 1.3847x over previous
#include <cuda_runtime.h>
#include <cuda_fp16.h>
#include <cstdint>

#define W_ 12
#define N_ 20000
#define C_ 64
#define E_ 320000
#define TOT (W_*N_*C_)   // 15,360,000
typedef unsigned long long ull;
typedef unsigned int uint;

// ---------------- scratch (device globals) ----------------------------------
// fp16-packed word layout: ull at [row][ks*4+q] = {h2(k0,k0+1), h2(k0+8,k0+9)}, k0=ks*16+2q
__device__ __align__(128) ull    g_Wp[7*128*16];         // inception weights [t][lane n][16]
__device__ __align__(128) ull    g_Xp[(size_t)W_*N_*16]; // x rows  [(w,n)][16]
__device__ __align__(128) ull    g_Gwp[2*12*8*4*32];     // gcn weights [(hop,w)][nt][ks][lane]
__device__ __align__(128) float  g_bc[128];
__device__ __align__(128) __half g_Hh [TOT];             // h buffer, fp16 channel-order (W,N,C)
__device__ __align__(128) uint   g_AggU[(size_t)W_*N_*32]; // aggregated h, fp16 MMA-A packed
__device__ int  g_deg   [W_*N_];
__device__ int  g_rowptr[W_*N_];
__device__ int  g_cur   [W_*N_];
__device__ int2 g_edge  [W_*E_];   // {src, wt bits}

struct WPtrs {
    const float* sw[4]; const float* sb[4];
    const float* gw[4]; const float* gb[4];
};

// ---------------- helpers ----------------------------------------------------
__device__ __forceinline__ uint pack_h2(float a, float b) {
    __half2 h = __floats2half2_rn(a, b);
    return *(uint*)&h;
}
__device__ __forceinline__ void mma_f16(float (&c)[4], uint a0, uint a1, uint a2, uint a3,
                                        uint b0, uint b1) {
    asm volatile(
        "mma.sync.aligned.m16n8k16.row.col.f32.f16.f16.f32 "
        "{%0,%1,%2,%3}, {%4,%5,%6,%7}, {%8,%9}, {%0,%1,%2,%3};\n"
        : "+f"(c[0]), "+f"(c[1]), "+f"(c[2]), "+f"(c[3])
        : "r"(a0), "r"(a1), "r"(a2), "r"(a3), "r"(b0), "r"(b1));
}
__device__ __forceinline__ void cpasync16(void* sdst, const void* gsrc) {
    uint s = (uint)__cvta_generic_to_shared(sdst);
    asm volatile("cp.async.ca.shared.global [%0], [%1], 16;" :: "r"(s), "l"(gsrc));
}
__device__ __forceinline__ void cp_commit() { asm volatile("cp.async.commit_group;"); }
__device__ __forceinline__ void cp_wait0()  { asm volatile("cp.async.wait_group 0;"); }
__device__ __forceinline__ float elu1(float v) { return v > 0.f ? v : expm1f(v); }

// ---------------- K0: build packed inception weights + bias ------------------
__global__ void prep_kernel(WPtrs p) {
    int gid = blockIdx.x * blockDim.x + threadIdx.x;
    if (gid < 7*128*16) {
        int t   = gid >> 11;
        int rem = gid & 2047;
        int n   = rem >> 4;
        int idx = rem & 15;
        int ks  = idx >> 2, q = idx & 3;
        int kw  = n >> 5, half = (n >> 4) & 1, ch = n & 15, k = 2*kw + 1;
        const float* src = half ? p.gw[kw] : p.sw[kw];
        int tt = t - 3 + kw;
        int k0 = ks*16 + 2*q;
        float v0 = 0.f, v1 = 0.f, v2 = 0.f, v3 = 0.f;
        if (tt >= 0 && tt < k) {
            v0 = src[(ch*64 + k0    )*k + tt];
            v1 = src[(ch*64 + k0 + 1)*k + tt];
            v2 = src[(ch*64 + k0 + 8)*k + tt];
            v3 = src[(ch*64 + k0 + 9)*k + tt];
        }
        g_Wp[gid] = (ull)pack_h2(v0, v1) | ((ull)pack_h2(v2, v3) << 32);
    }
    if (gid < 128) {
        int j = gid;
        int kw = j >> 5; int half = (j >> 4) & 1; int ch = j & 15;
        g_bc[j] = half ? p.gb[kw][ch] : p.sb[kw][ch];
    }
}

// ---------------- K0c: pack gcn weights as MMA B-fragments -------------------
__global__ void prep_gw_kernel(const float* __restrict__ gw) {
    int gid = blockIdx.x*256 + threadIdx.x;
    if (gid >= 2*12*8*4*32) return;
    int lane = gid & 31;
    int ks   = (gid >> 5) & 3;
    int nt   = (gid >> 7) & 7;
    int rest = gid >> 10;            // hop*12 + w
    int n = nt*8 + (lane >> 2);
    int q = lane & 3;
    int k0 = ks*16 + 2*q;
    const float* Wb = gw + (size_t)rest*64*64;
    float v0 = Wb[(k0    )*64 + n];
    float v1 = Wb[(k0 + 1)*64 + n];
    float v2 = Wb[(k0 + 8)*64 + n];
    float v3 = Wb[(k0 + 9)*64 + n];
    g_Gwp[gid] = (ull)pack_h2(v0, v1) | ((ull)pack_h2(v2, v3) << 32);
}

// ---------------- K0b: pack x into fp16 A-fragment pairs ---------------------
__global__ void pack_x_kernel(const float* __restrict__ x) {
    int gid = blockIdx.x*256 + threadIdx.x;
    if (gid >= W_*N_*16) return;
    int row = gid >> 4, idx = gid & 15;
    int ks = idx >> 2, q = idx & 3;
    int k0 = ks*16 + 2*q;
    const float* xr = x + (size_t)row*64;
    float2 lo = *(const float2*)(xr + k0);
    float2 hi = *(const float2*)(xr + k0 + 8);
    g_Xp[gid] = (ull)pack_h2(lo.x, lo.y) | ((ull)pack_h2(hi.x, hi.y) << 32);
}

// ---------------- K1: inception via fp16 mma ---------------------------------
#define PAD 18
#define XS_ULL (18*16*PAD)
#define WS_ULL (128*PAD)
#define SMEM_BYTES ((XS_ULL + 2*WS_ULL)*8)

__global__ void __launch_bounds__(256) incep_mma_kernel() {
    extern __shared__ ull sm[];
    ull* Xs = sm;                 // [wi(18)][nloc(16)][PAD]
    ull* Ws = sm + XS_ULL;        // [2][n(128)][PAD]

    int tid = threadIdx.x;
    int n0  = blockIdx.x * 16;

    {
        const int zl[6] = {0,1,2,15,16,17};
        for (int idx = tid; idx < 6*16*PAD; idx += 256) {
            int wi = zl[idx / (16*PAD)];
            Xs[wi*(16*PAD) + (idx % (16*PAD))] = 0ull;
        }
    }
    for (int idx = tid; idx < 12*16*8; idx += 256) {
        int c = idx & 7, row = idx >> 3;
        int wrow = row >> 4, nloc = row & 15;
        cpasync16(&Xs[((wrow+3)*16 + nloc)*PAD + c*2],
                  g_Xp + ((size_t)(wrow*N_ + n0 + nloc)*16 + c*2));
    }
    for (int idx = tid; idx < 128*8; idx += 256) {
        int c = idx & 7, n = idx >> 3;
        cpasync16(&Ws[n*PAD + c*2], g_Wp + ((size_t)n*16 + c*2));
    }
    cp_commit();
    cp_wait0();
    __syncthreads();

    int lane = tid & 31, wid = tid >> 5;
    int mg = wid >> 1, par = wid & 1;
    int g = lane >> 2, q = lane & 3;

    float acc[3][8][4];
    #pragma unroll
    for (int j = 0; j < 3; j++)
        #pragma unroll
        for (int u = 0; u < 8; u++)
            #pragma unroll
            for (int c = 0; c < 4; c++) acc[j][u][c] = 0.f;

    for (int t = 0; t < 7; t++) {
        if (t < 6) {
            ull* Wn = Ws + ((t+1)&1)*WS_ULL;
            for (int idx = tid; idx < 128*8; idx += 256) {
                int c = idx & 7, n = idx >> 3;
                cpasync16(&Wn[n*PAD + c*2], g_Wp + ((size_t)((t+1)*128 + n)*16 + c*2));
            }
            cp_commit();
        }
        const ull* Wc = Ws + (t&1)*WS_ULL;
        int wibase = 3*mg + t;

        #pragma unroll
        for (int ks = 0; ks < 4; ks++) {
            uint a0[3], a1[3], a2[3], a3[3];
            #pragma unroll
            for (int j = 0; j < 3; j++) {
                ull v0 = Xs[((wibase+j)*16 + g    )*PAD + ks*4 + q];
                ull v1 = Xs[((wibase+j)*16 + g + 8)*PAD + ks*4 + q];
                a0[j] = (uint)v0; a2[j] = (uint)(v0 >> 32);
                a1[j] = (uint)v1; a3[j] = (uint)(v1 >> 32);
            }
            #pragma unroll
            for (int u = 0; u < 8; u++) {
                int nt = 2*u + par;
                int kw = nt >> 2;
                if (t >= 3-kw && t <= 3+kw) {
                    ull bw = Wc[(nt*8 + g)*PAD + ks*4 + q];
                    uint b0 = (uint)bw, b1 = (uint)(bw >> 32);
                    mma_f16(acc[0][u], a0[0], a1[0], a2[0], a3[0], b0, b1);
                    mma_f16(acc[1][u], a0[1], a1[1], a2[1], a3[1], b0, b1);
                    mma_f16(acc[2][u], a0[2], a1[2], a2[2], a3[2], b0, b1);
                }
            }
        }
        if (t < 6) cp_wait0();
        __syncthreads();
    }

    // epilogue: bias + GLU, write g_Hh (fp16, channel order)
    #pragma unroll
    for (int j = 0; j < 3; j++) {
        int w = 3*mg + j;
        #pragma unroll
        for (int us = 0; us < 8; us += 2) {
            int nts = 2*us + par;
            float2 bs = *(const float2*)&g_bc[nts*8 + 2*q];
            float2 bg = *(const float2*)&g_bc[(nts+2)*8 + 2*q];
            float s0 = acc[j][us][0] + bs.x, s1 = acc[j][us][1] + bs.y;
            float s2 = acc[j][us][2] + bs.x, s3 = acc[j][us][3] + bs.y;
            float g0 = acc[j][us+1][0] + bg.x, g1 = acc[j][us+1][1] + bg.y;
            float g2 = acc[j][us+1][2] + bg.x, g3 = acc[j][us+1][3] + bg.y;
            float o0 = fmaxf(s0, 0.f) * (1.f/(1.f + __expf(-g0)));
            float o1 = fmaxf(s1, 0.f) * (1.f/(1.f + __expf(-g1)));
            float o2 = fmaxf(s2, 0.f) * (1.f/(1.f + __expf(-g2)));
            float o3 = fmaxf(s3, 0.f) * (1.f/(1.f + __expf(-g3)));
            int kw = nts >> 2;
            int cout = kw*16 + par*8 + 2*q;
            *(__half2*)&g_Hh[((size_t)w*N_ + n0 + g    )*64 + cout] = __floats2half2_rn(o0, o1);
            *(__half2*)&g_Hh[((size_t)w*N_ + n0 + g + 8)*64 + cout] = __floats2half2_rn(o2, o3);
        }
    }
}

// ---------------- CSR build (once) ------------------------------------------
__global__ void zerodeg_kernel() {
    int i = blockIdx.x*blockDim.x + threadIdx.x;
    if (i < W_*N_) g_deg[i] = 0;
}

__global__ void hist_kernel(const int* __restrict__ ei) {
    int g = blockIdx.x*blockDim.x + threadIdx.x;
    if (g >= W_*E_) return;
    int w = g / E_;
    int e = g - w*E_;
    int dst = ei[(size_t)(2*w+1)*E_ + e];
    atomicAdd(&g_deg[w*N_ + dst], 1);
}

__global__ void __launch_bounds__(512) scan_kernel() {
    __shared__ int wsum[16];
    int w = blockIdx.x;
    int t = threadIdx.x, lane = t & 31, wid = t >> 5;
    const int* deg = g_deg + w*N_;
    int base = t * 40;
    int s = 0;
    for (int k = 0; k < 40; k++) {
        int idx = base + k;
        if (idx < N_) s += deg[idx];
    }
    int v = s;
    #pragma unroll
    for (int d = 1; d < 32; d <<= 1) {
        int o = __shfl_up_sync(0xffffffffu, v, d);
        if (lane >= d) v += o;
    }
    if (lane == 31) wsum[wid] = v;
    __syncthreads();
    if (t == 0) {
        int r = 0;
        #pragma unroll
        for (int qq = 0; qq < 16; qq++) { int xq = wsum[qq]; wsum[qq] = r; r += xq; }
    }
    __syncthreads();
    int run = wsum[wid] + (v - s);
    for (int k = 0; k < 40; k++) {
        int idx = base + k;
        if (idx < N_) {
            int d = deg[idx];
            g_rowptr[w*N_ + idx] = run;
            g_cur   [w*N_ + idx] = run;
            run += d;
        }
    }
}

__global__ void place_kernel(const int* __restrict__ ei, const float* __restrict__ ewt) {
    int g = blockIdx.x*blockDim.x + threadIdx.x;
    if (g >= W_*E_) return;
    int w = g / E_;
    int e = g - w*E_;
    int src = ei[(size_t)(2*w)  *E_ + e];
    int dst = ei[(size_t)(2*w+1)*E_ + e];
    float wt = ewt[(size_t)w*E_ + e];
    int pos = atomicAdd(&g_cur[w*N_ + dst], 1);
    g_edge[(size_t)w*E_ + pos] = make_int2(src, __float_as_int(wt));
}

// ---------------- K4: gather-aggregate with shuffle-broadcast edges ---------
__global__ void __launch_bounds__(256) agg_kernel() {
    int gid = blockIdx.x*256 + threadIdx.x;
    int q  = gid & 7;           // 8-channel slice
    int wn = gid >> 3;
    int w  = wn / N_;
    int lane = threadIdx.x & 31;
    uint gmask = 0xffu << (lane & 24);

    int beg = g_rowptr[wn];
    int deg = g_deg[wn];
    const int2*  ed = g_edge + (size_t)w*E_;
    const uint4* Hb = (const uint4*)g_Hh + (size_t)w*N_*8 + q;

    float a0=0.f,a1=0.f,a2=0.f,a3=0.f,a4=0.f,a5=0.f,a6=0.f,a7=0.f;
    for (int base = 0; base < deg; base += 8) {
        int lim = deg - base;
        int2 pr = make_int2(0, 0);
        if (q < lim) pr = ed[beg + base + q];
        int m = lim < 8 ? lim : 8;
        #pragma unroll
        for (int j = 0; j < 8; j++) {
            if (j < m) {
                int   src = __shfl_sync(gmask, pr.x, j, 8);
                float wt  = __int_as_float(__shfl_sync(gmask, pr.y, j, 8));
                uint4 v = Hb[(size_t)src*8];
                const __half2* hp = (const __half2*)&v;
                float2 f0 = __half22float2(hp[0]);
                float2 f1 = __half22float2(hp[1]);
                float2 f2 = __half22float2(hp[2]);
                float2 f3 = __half22float2(hp[3]);
                a0 = fmaf(wt, f0.x, a0); a1 = fmaf(wt, f0.y, a1);
                a2 = fmaf(wt, f1.x, a2); a3 = fmaf(wt, f1.y, a3);
                a4 = fmaf(wt, f2.x, a4); a5 = fmaf(wt, f2.y, a5);
                a6 = fmaf(wt, f3.x, a6); a7 = fmaf(wt, f3.y, a7);
            }
        }
    }
    // write fp16, MMA-A packed layout:
    // word kk=ks*4+qq holds {h2(16ks+2qq, +1), h2(16ks+2qq+8, +9)}; this thread's
    // channels q*8..q*8+7 are the (q&1 ? hi : lo) halves of words (q>>1)*4 + 0..3
    int s = q >> 1, odd = q & 1;
    uint* o = g_AggU + (size_t)wn*32;
    o[(s*4 + 0)*2 + odd] = pack_h2(a0, a1);
    o[(s*4 + 1)*2 + odd] = pack_h2(a2, a3);
    o[(s*4 + 2)*2 + odd] = pack_h2(a4, a5);
    o[(s*4 + 3)*2 + odd] = pack_h2(a6, a7);
}

// ---------------- K5: tensor-core gemm + bias + ELU (+residual) -------------
__global__ void __launch_bounds__(256) gemm_mma_kernel(const float* __restrict__ gb, int hop,
                                                       const float* __restrict__ x,
                                                       float* __restrict__ out) {
    int w = blockIdx.y;
    int wid = threadIdx.x >> 5, lane = threadIdx.x & 31;
    int g = lane >> 2, q = lane & 3;
    int n0 = blockIdx.x*256 + wid*32;
    if (n0 >= N_) return;

    const ull* A  = (const ull*)g_AggU + (size_t)w*N_*16;
    const ull* Wm = g_Gwp + ((size_t)(hop*W_ + w))*8*4*32;
    const float* bias = gb + (size_t)(hop*W_ + w)*64;

    float acc[2][8][4];
    #pragma unroll
    for (int nt = 0; nt < 8; nt++) {
        float2 bv = *(const float2*)&bias[nt*8 + 2*q];
        #pragma unroll
        for (int mt = 0; mt < 2; mt++) {
            acc[mt][nt][0] = bv.x; acc[mt][nt][1] = bv.y;
            acc[mt][nt][2] = bv.x; acc[mt][nt][3] = bv.y;
        }
    }

    int r0 = n0 + g, r1 = n0 + g + 8, r2 = n0 + 16 + g, r3 = n0 + 24 + g;
    #pragma unroll
    for (int ks = 0; ks < 4; ks++) {
        int kk = ks*4 + q;
        ull v0 = (r0 < N_) ? A[(size_t)r0*16 + kk] : 0ull;
        ull v1 = (r1 < N_) ? A[(size_t)r1*16 + kk] : 0ull;
        ull v2 = (r2 < N_) ? A[(size_t)r2*16 + kk] : 0ull;
        ull v3 = (r3 < N_) ? A[(size_t)r3*16 + kk] : 0ull;
        uint a00 = (uint)v0, a02 = (uint)(v0 >> 32);
        uint a01 = (uint)v1, a03 = (uint)(v1 >> 32);
        uint a10 = (uint)v2, a12 = (uint)(v2 >> 32);
        uint a11 = (uint)v3, a13 = (uint)(v3 >> 32);
        #pragma unroll
        for (int nt = 0; nt < 8; nt++) {
            ull bw = Wm[(nt*4 + ks)*32 + lane];
            uint b0 = (uint)bw, b1 = (uint)(bw >> 32);
            mma_f16(acc[0][nt], a00, a01, a02, a03, b0, b1);
            mma_f16(acc[1][nt], a10, a11, a12, a13, b0, b1);
        }
    }

    #pragma unroll
    for (int mt = 0; mt < 2; mt++) {
        int rA = n0 + mt*16 + g, rB = rA + 8;
        #pragma unroll
        for (int nt = 0; nt < 8; nt++) {
            float c0 = elu1(acc[mt][nt][0]);
            float c1 = elu1(acc[mt][nt][1]);
            float c2 = elu1(acc[mt][nt][2]);
            float c3 = elu1(acc[mt][nt][3]);
            int cout0 = nt*8 + 2*q;
            if (out) {
                if (rA < N_) {
                    size_t oi = ((size_t)w*N_ + rA)*64 + cout0;
                    float2 xv = *(const float2*)&x[oi];
                    *(float2*)&out[oi] = make_float2(c0 + xv.x, c1 + xv.y);
                }
                if (rB < N_) {
                    size_t oi = ((size_t)w*N_ + rB)*64 + cout0;
                    float2 xv = *(const float2*)&x[oi];
                    *(float2*)&out[oi] = make_float2(c2 + xv.x, c3 + xv.y);
                }
            } else {
                if (rA < N_)
                    *(__half2*)&g_Hh[((size_t)w*N_ + rA)*64 + cout0] = __floats2half2_rn(c0, c1);
                if (rB < N_)
                    *(__half2*)&g_Hh[((size_t)w*N_ + rB)*64 + cout0] = __floats2half2_rn(c2, c3);
            }
        }
    }
}

// ---------------- launch -----------------------------------------------------
extern "C" void kernel_launch(void* const* d_in, const int* in_sizes, int n_in,
                              void* d_out, int out_size) {
    const float* x  = (const float*)d_in[0];
    const int*   ei = (const int*)  d_in[1];
    const float* ew = (const float*)d_in[2];

    WPtrs p;
    if (in_sizes[5] == 1024) {
        int idx = 3;
        for (int t = 0; t < 4; t++) {
            p.sw[t] = (const float*)d_in[idx++];
            p.sb[t] = (const float*)d_in[idx++];
            p.gw[t] = (const float*)d_in[idx++];
            p.gb[t] = (const float*)d_in[idx++];
        }
    } else {
        int idx = 3;
        for (int t = 0; t < 4; t++) {
            p.sw[t] = (const float*)d_in[idx++];
            p.sb[t] = (const float*)d_in[idx++];
        }
        for (int t = 0; t < 4; t++) {
            p.gw[t] = (const float*)d_in[idx++];
            p.gb[t] = (const float*)d_in[idx++];
        }
    }
    const float* gw = (const float*)d_in[19];
    const float* gb = (const float*)d_in[20];
    float* out = (float*)d_out;

    static bool attr_done = false;
    if (!attr_done) {
        cudaFuncSetAttribute(incep_mma_kernel,
                             cudaFuncAttributeMaxDynamicSharedMemorySize, SMEM_BYTES);
        attr_done = true;
    }

    prep_kernel<<<(7*128*16 + 255)/256, 256>>>(p);
    prep_gw_kernel<<<(2*12*8*4*32 + 255)/256, 256>>>(gw);
    pack_x_kernel<<<(W_*N_*16 + 255)/256, 256>>>(x);
    incep_mma_kernel<<<N_/16, 256, SMEM_BYTES>>>();

    zerodeg_kernel<<<(W_*N_ + 255)/256, 256>>>();
    hist_kernel<<<(W_*E_ + 255)/256, 256>>>(ei);
    scan_kernel<<<W_, 512>>>();
    place_kernel<<<(W_*E_ + 255)/256, 256>>>(ei, ew);

    for (int hop = 0; hop < 2; hop++) {
        agg_kernel<<<W_*N_*8/256, 256>>>();
        gemm_mma_kernel<<<dim3((N_ + 255)/256, W_), 256>>>(gb, hop, x,
                                                           hop == 1 ? out : nullptr);
    }
}

// round 9
// speedup vs baseline: 2.8704x; 1.1151x over previous
#include <cuda_runtime.h>
#include <cuda_fp16.h>
#include <cstdint>

#define W_ 12
#define N_ 20000
#define C_ 64
#define E_ 320000
#define TOT (W_*N_*C_)   // 15,360,000
typedef unsigned long long ull;
typedef unsigned int uint;

// ---------------- scratch (device globals) ----------------------------------
__device__ __align__(128) __half g_WpH[7*128*64];          // inception weights, plain [t][n][64]
__device__ __align__(128) __half g_XpH[(size_t)W_*N_*64];  // x rows fp16, plain [(w,n)][64]
__device__ __align__(128) ull    g_Gwp[2*12*8*4*32];       // gcn weights [(hop,w)][nt][ks][lane]
__device__ __align__(128) float  g_bc[128];
__device__ __align__(128) __half g_Hh [TOT];               // h buffer, fp16 channel-order (W,N,C)
__device__ __align__(128) uint   g_AggU[(size_t)W_*N_*32]; // aggregated h, fp16 MMA-A packed
__device__ int  g_deg   [W_*N_];
__device__ int  g_rowptr[W_*N_];
__device__ int  g_cur   [W_*N_];
__device__ int2 g_edge  [W_*E_];   // {src, wt bits}

struct WPtrs {
    const float* sw[4]; const float* sb[4];
    const float* gw[4]; const float* gb[4];
};

// ---------------- helpers ----------------------------------------------------
__device__ __forceinline__ uint pack_h2(float a, float b) {
    __half2 h = __floats2half2_rn(a, b);
    return *(uint*)&h;
}
__device__ __forceinline__ void mma_f16(float (&c)[4], uint a0, uint a1, uint a2, uint a3,
                                        uint b0, uint b1) {
    asm volatile(
        "mma.sync.aligned.m16n8k16.row.col.f32.f16.f16.f32 "
        "{%0,%1,%2,%3}, {%4,%5,%6,%7}, {%8,%9}, {%0,%1,%2,%3};\n"
        : "+f"(c[0]), "+f"(c[1]), "+f"(c[2]), "+f"(c[3])
        : "r"(a0), "r"(a1), "r"(a2), "r"(a3), "r"(b0), "r"(b1));
}
__device__ __forceinline__ void ldm_x4(uint& r0, uint& r1, uint& r2, uint& r3, uint a) {
    asm volatile("ldmatrix.sync.aligned.m8n8.x4.shared.b16 {%0,%1,%2,%3}, [%4];"
        : "=r"(r0), "=r"(r1), "=r"(r2), "=r"(r3) : "r"(a));
}
__device__ __forceinline__ void ldm_x2(uint& r0, uint& r1, uint a) {
    asm volatile("ldmatrix.sync.aligned.m8n8.x2.shared.b16 {%0,%1}, [%2];"
        : "=r"(r0), "=r"(r1) : "r"(a));
}
__device__ __forceinline__ void cpasync16(void* sdst, const void* gsrc) {
    uint s = (uint)__cvta_generic_to_shared(sdst);
    asm volatile("cp.async.ca.shared.global [%0], [%1], 16;" :: "r"(s), "l"(gsrc));
}
__device__ __forceinline__ void cp_commit() { asm volatile("cp.async.commit_group;"); }
__device__ __forceinline__ void cp_wait0()  { asm volatile("cp.async.wait_group 0;"); }
__device__ __forceinline__ float elu1(float v) { return v > 0.f ? v : expm1f(v); }

// ---------------- K0: build plain fp16 inception weights + bias --------------
__global__ void prep_kernel(WPtrs p) {
    int gid = blockIdx.x * blockDim.x + threadIdx.x;
    if (gid < 7*128*64) {
        int t   = gid >> 13;           // 128*64 = 8192
        int rem = gid & 8191;
        int n   = rem >> 6, c = rem & 63;
        int kw  = n >> 5, half = (n >> 4) & 1, ch = n & 15, k = 2*kw + 1;
        int tt  = t - 3 + kw;
        float v = 0.f;
        if (tt >= 0 && tt < k)
            v = (half ? p.gw[kw] : p.sw[kw])[(ch*64 + c)*k + tt];
        g_WpH[gid] = __float2half(v);
    }
    if (gid < 128) {
        int j = gid;
        int kw = j >> 5; int half = (j >> 4) & 1; int ch = j & 15;
        g_bc[j] = half ? p.gb[kw][ch] : p.sb[kw][ch];
    }
}

// ---------------- K0c: pack gcn weights as MMA B-fragments -------------------
__global__ void prep_gw_kernel(const float* __restrict__ gw) {
    int gid = blockIdx.x*256 + threadIdx.x;
    if (gid >= 2*12*8*4*32) return;
    int lane = gid & 31;
    int ks   = (gid >> 5) & 3;
    int nt   = (gid >> 7) & 7;
    int rest = gid >> 10;            // hop*12 + w
    int n = nt*8 + (lane >> 2);
    int q = lane & 3;
    int k0 = ks*16 + 2*q;
    const float* Wb = gw + (size_t)rest*64*64;
    float v0 = Wb[(k0    )*64 + n];
    float v1 = Wb[(k0 + 1)*64 + n];
    float v2 = Wb[(k0 + 8)*64 + n];
    float v3 = Wb[(k0 + 9)*64 + n];
    g_Gwp[gid] = (ull)pack_h2(v0, v1) | ((ull)pack_h2(v2, v3) << 32);
}

// ---------------- K0b: pack x into plain fp16 rows ---------------------------
__global__ void pack_x_kernel(const float4* __restrict__ x4) {
    int gid = blockIdx.x*256 + threadIdx.x;
    if (gid >= W_*N_*8) return;
    int row = gid >> 3, c = gid & 7;
    float4 f0 = x4[(size_t)row*16 + c*2];
    float4 f1 = x4[(size_t)row*16 + c*2 + 1];
    uint4 o;
    o.x = pack_h2(f0.x, f0.y); o.y = pack_h2(f0.z, f0.w);
    o.z = pack_h2(f1.x, f1.y); o.w = pack_h2(f1.z, f1.w);
    ((uint4*)g_XpH)[(size_t)row*8 + c] = o;
}

// ---------------- K1: inception via fp16 mma + ldmatrix ----------------------
// Block: 16 nodes, 256 threads (8 warps). Smem rows plain fp16, 144B stride
// (granule 9i+c mod 8 distinct => conflict-free LDSM).
#define XROWB 144
#define XS_BYTES (18*16*XROWB)       // 41472
#define WS_BYTES (128*XROWB)         // 18432
#define SMEM_BYTES (XS_BYTES + 2*WS_BYTES)

__global__ void __launch_bounds__(256, 2) incep_mma_kernel() {
    extern __shared__ char sm[];
    char* Xs = sm;                    // [wi(18)][nloc(16)] rows
    char* Ws = sm + XS_BYTES;         // [2][n(128)] rows

    int tid = threadIdx.x;
    int n0  = blockIdx.x * 16;

    // zero pad rows (wi = 0,1,2,15,16,17), 9 uint4 per 144B row
    {
        const int zl[6] = {0,1,2,15,16,17};
        for (int idx = tid; idx < 6*16*9; idx += 256) {
            int r = idx / 9, c = idx - r*9;
            int wi = zl[r >> 4], nloc = r & 15;
            ((uint4*)(Xs + (wi*16 + nloc)*XROWB))[c] = make_uint4(0,0,0,0);
        }
    }
    // fill X rows (12w x 16n x 8 chunks of 16B)
    for (int idx = tid; idx < 12*16*8; idx += 256) {
        int c = idx & 7, row = idx >> 3;
        int wrow = row >> 4, nloc = row & 15;
        cpasync16(Xs + ((wrow+3)*16 + nloc)*XROWB + c*16,
                  g_XpH + ((size_t)(wrow*N_ + n0 + nloc))*64 + c*8);
    }
    // W stage 0
    for (int idx = tid; idx < 128*8; idx += 256) {
        int c = idx & 7, n = idx >> 3;
        cpasync16(Ws + n*XROWB + c*16, g_WpH + ((size_t)n)*64 + c*8);
    }
    cp_commit();
    cp_wait0();
    __syncthreads();

    int lane = tid & 31, wid = tid >> 5;
    int mg = wid >> 1, par = wid & 1;
    int g = lane >> 2, q = lane & 3;

    uint xsB = (uint)__cvta_generic_to_shared(Xs);
    uint wsB = (uint)__cvta_generic_to_shared(Ws);
    // A: lanes 0-7 rows m0-7 @k0 | 8-15 rows m8-15 @k0 | 16-23 m0-7 @k0+16B | 24-31 m8-15 @+16B
    uint aA0 = xsB + (lane & 15)*XROWB + (lane >> 4)*16;
    // B (x2, non-trans): lanes 0-7 rows n0-7 @k0 | 8-15 rows n0-7 @k0+16B
    uint bA0 = wsB + (lane & 7)*XROWB + ((lane >> 3) & 1)*16;

    float acc[3][8][4];
    #pragma unroll
    for (int j = 0; j < 3; j++)
        #pragma unroll
        for (int u = 0; u < 8; u++)
            #pragma unroll
            for (int c = 0; c < 4; c++) acc[j][u][c] = 0.f;

    for (int t = 0; t < 7; t++) {
        if (t < 6) {
            char* Wn = Ws + ((t+1)&1)*WS_BYTES;
            for (int idx = tid; idx < 128*8; idx += 256) {
                int c = idx & 7, n = idx >> 3;
                cpasync16(Wn + n*XROWB + c*16, g_WpH + ((size_t)((t+1)*128 + n))*64 + c*8);
            }
            cp_commit();
        }
        uint wB = bA0 + (t&1)*WS_BYTES;
        uint aB = aA0 + (3*mg + t)*(16*XROWB);

        #pragma unroll
        for (int ks = 0; ks < 4; ks++) {
            uint a0[3], a1[3], a2[3], a3[3];
            #pragma unroll
            for (int j = 0; j < 3; j++)
                ldm_x4(a0[j], a1[j], a2[j], a3[j], aB + j*(16*XROWB) + ks*32);
            #pragma unroll
            for (int u = 0; u < 8; u++) {
                int nt = 2*u + par;
                int kw = nt >> 2;
                if (t >= 3-kw && t <= 3+kw) {
                    uint b0, b1;
                    ldm_x2(b0, b1, wB + nt*(8*XROWB) + ks*32);
                    mma_f16(acc[0][u], a0[0], a1[0], a2[0], a3[0], b0, b1);
                    mma_f16(acc[1][u], a0[1], a1[1], a2[1], a3[1], b0, b1);
                    mma_f16(acc[2][u], a0[2], a1[2], a2[2], a3[2], b0, b1);
                }
            }
        }
        if (t < 6) cp_wait0();
        __syncthreads();
    }

    // epilogue: bias + GLU, write g_Hh (fp16, channel order)
    #pragma unroll
    for (int j = 0; j < 3; j++) {
        int w = 3*mg + j;
        #pragma unroll
        for (int us = 0; us < 8; us += 2) {
            int nts = 2*us + par;
            float2 bs = *(const float2*)&g_bc[nts*8 + 2*q];
            float2 bg = *(const float2*)&g_bc[(nts+2)*8 + 2*q];
            float s0 = acc[j][us][0] + bs.x, s1 = acc[j][us][1] + bs.y;
            float s2 = acc[j][us][2] + bs.x, s3 = acc[j][us][3] + bs.y;
            float g0 = acc[j][us+1][0] + bg.x, g1 = acc[j][us+1][1] + bg.y;
            float g2 = acc[j][us+1][2] + bg.x, g3 = acc[j][us+1][3] + bg.y;
            float o0 = fmaxf(s0, 0.f) * (1.f/(1.f + __expf(-g0)));
            float o1 = fmaxf(s1, 0.f) * (1.f/(1.f + __expf(-g1)));
            float o2 = fmaxf(s2, 0.f) * (1.f/(1.f + __expf(-g2)));
            float o3 = fmaxf(s3, 0.f) * (1.f/(1.f + __expf(-g3)));
            int kw = nts >> 2;
            int cout = kw*16 + par*8 + 2*q;
            *(__half2*)&g_Hh[((size_t)w*N_ + n0 + g    )*64 + cout] = __floats2half2_rn(o0, o1);
            *(__half2*)&g_Hh[((size_t)w*N_ + n0 + g + 8)*64 + cout] = __floats2half2_rn(o2, o3);
        }
    }
}

// ---------------- CSR build (once) ------------------------------------------
__global__ void zerodeg_kernel() {
    int i = blockIdx.x*blockDim.x + threadIdx.x;
    if (i < W_*N_) g_deg[i] = 0;
}

__global__ void hist_kernel(const int* __restrict__ ei) {
    int g = blockIdx.x*blockDim.x + threadIdx.x;
    if (g >= W_*E_) return;
    int w = g / E_;
    int e = g - w*E_;
    int dst = ei[(size_t)(2*w+1)*E_ + e];
    atomicAdd(&g_deg[w*N_ + dst], 1);
}

__global__ void __launch_bounds__(512) scan_kernel() {
    __shared__ int wsum[16];
    int w = blockIdx.x;
    int t = threadIdx.x, lane = t & 31, wid = t >> 5;
    const int* deg = g_deg + w*N_;
    int base = t * 40;
    int s = 0;
    for (int k = 0; k < 40; k++) {
        int idx = base + k;
        if (idx < N_) s += deg[idx];
    }
    int v = s;
    #pragma unroll
    for (int d = 1; d < 32; d <<= 1) {
        int o = __shfl_up_sync(0xffffffffu, v, d);
        if (lane >= d) v += o;
    }
    if (lane == 31) wsum[wid] = v;
    __syncthreads();
    if (t == 0) {
        int r = 0;
        #pragma unroll
        for (int qq = 0; qq < 16; qq++) { int xq = wsum[qq]; wsum[qq] = r; r += xq; }
    }
    __syncthreads();
    int run = wsum[wid] + (v - s);
    for (int k = 0; k < 40; k++) {
        int idx = base + k;
        if (idx < N_) {
            int d = deg[idx];
            g_rowptr[w*N_ + idx] = run;
            g_cur   [w*N_ + idx] = run;
            run += d;
        }
    }
}

__global__ void place_kernel(const int* __restrict__ ei, const float* __restrict__ ewt) {
    int g = blockIdx.x*blockDim.x + threadIdx.x;
    if (g >= W_*E_) return;
    int w = g / E_;
    int e = g - w*E_;
    int src = ei[(size_t)(2*w)  *E_ + e];
    int dst = ei[(size_t)(2*w+1)*E_ + e];
    float wt = ewt[(size_t)w*E_ + e];
    int pos = atomicAdd(&g_cur[w*N_ + dst], 1);
    g_edge[(size_t)w*E_ + pos] = make_int2(src, __float_as_int(wt));
}

// ---------------- K4: gather-aggregate with shuffle-broadcast edges ---------
__global__ void __launch_bounds__(256) agg_kernel() {
    int gid = blockIdx.x*256 + threadIdx.x;
    int q  = gid & 7;           // 8-channel slice
    int wn = gid >> 3;
    int w  = wn / N_;
    int lane = threadIdx.x & 31;
    uint gmask = 0xffu << (lane & 24);

    int beg = g_rowptr[wn];
    int deg = g_deg[wn];
    const int2*  ed = g_edge + (size_t)w*E_;
    const uint4* Hb = (const uint4*)g_Hh + (size_t)w*N_*8 + q;

    float a0=0.f,a1=0.f,a2=0.f,a3=0.f,a4=0.f,a5=0.f,a6=0.f,a7=0.f;
    for (int base = 0; base < deg; base += 8) {
        int lim = deg - base;
        int2 pr = make_int2(0, 0);
        if (q < lim) pr = ed[beg + base + q];
        int m = lim < 8 ? lim : 8;
        #pragma unroll
        for (int j = 0; j < 8; j++) {
            if (j < m) {
                int   src = __shfl_sync(gmask, pr.x, j, 8);
                float wt  = __int_as_float(__shfl_sync(gmask, pr.y, j, 8));
                uint4 v = Hb[(size_t)src*8];
                const __half2* hp = (const __half2*)&v;
                float2 f0 = __half22float2(hp[0]);
                float2 f1 = __half22float2(hp[1]);
                float2 f2 = __half22float2(hp[2]);
                float2 f3 = __half22float2(hp[3]);
                a0 = fmaf(wt, f0.x, a0); a1 = fmaf(wt, f0.y, a1);
                a2 = fmaf(wt, f1.x, a2); a3 = fmaf(wt, f1.y, a3);
                a4 = fmaf(wt, f2.x, a4); a5 = fmaf(wt, f2.y, a5);
                a6 = fmaf(wt, f3.x, a6); a7 = fmaf(wt, f3.y, a7);
            }
        }
    }
    int s = q >> 1, odd = q & 1;
    uint* o = g_AggU + (size_t)wn*32;
    o[(s*4 + 0)*2 + odd] = pack_h2(a0, a1);
    o[(s*4 + 1)*2 + odd] = pack_h2(a2, a3);
    o[(s*4 + 2)*2 + odd] = pack_h2(a4, a5);
    o[(s*4 + 3)*2 + odd] = pack_h2(a6, a7);
}

// ---------------- K5: tensor-core gemm + bias + ELU (+residual) -------------
__global__ void __launch_bounds__(256) gemm_mma_kernel(const float* __restrict__ gb, int hop,
                                                       const float* __restrict__ x,
                                                       float* __restrict__ out) {
    int w = blockIdx.y;
    int wid = threadIdx.x >> 5, lane = threadIdx.x & 31;
    int g = lane >> 2, q = lane & 3;
    int n0 = blockIdx.x*256 + wid*32;
    if (n0 >= N_) return;

    const ull* A  = (const ull*)g_AggU + (size_t)w*N_*16;
    const ull* Wm = g_Gwp + ((size_t)(hop*W_ + w))*8*4*32;
    const float* bias = gb + (size_t)(hop*W_ + w)*64;

    float acc[2][8][4];
    #pragma unroll
    for (int nt = 0; nt < 8; nt++) {
        float2 bv = *(const float2*)&bias[nt*8 + 2*q];
        #pragma unroll
        for (int mt = 0; mt < 2; mt++) {
            acc[mt][nt][0] = bv.x; acc[mt][nt][1] = bv.y;
            acc[mt][nt][2] = bv.x; acc[mt][nt][3] = bv.y;
        }
    }

    int r0 = n0 + g, r1 = n0 + g + 8, r2 = n0 + 16 + g, r3 = n0 + 24 + g;
    #pragma unroll
    for (int ks = 0; ks < 4; ks++) {
        int kk = ks*4 + q;
        ull v0 = (r0 < N_) ? A[(size_t)r0*16 + kk] : 0ull;
        ull v1 = (r1 < N_) ? A[(size_t)r1*16 + kk] : 0ull;
        ull v2 = (r2 < N_) ? A[(size_t)r2*16 + kk] : 0ull;
        ull v3 = (r3 < N_) ? A[(size_t)r3*16 + kk] : 0ull;
        uint a00 = (uint)v0, a02 = (uint)(v0 >> 32);
        uint a01 = (uint)v1, a03 = (uint)(v1 >> 32);
        uint a10 = (uint)v2, a12 = (uint)(v2 >> 32);
        uint a11 = (uint)v3, a13 = (uint)(v3 >> 32);
        #pragma unroll
        for (int nt = 0; nt < 8; nt++) {
            ull bw = Wm[(nt*4 + ks)*32 + lane];
            uint b0 = (uint)bw, b1 = (uint)(bw >> 32);
            mma_f16(acc[0][nt], a00, a01, a02, a03, b0, b1);
            mma_f16(acc[1][nt], a10, a11, a12, a13, b0, b1);
        }
    }

    #pragma unroll
    for (int mt = 0; mt < 2; mt++) {
        int rA = n0 + mt*16 + g, rB = rA + 8;
        #pragma unroll
        for (int nt = 0; nt < 8; nt++) {
            float c0 = elu1(acc[mt][nt][0]);
            float c1 = elu1(acc[mt][nt][1]);
            float c2 = elu1(acc[mt][nt][2]);
            float c3 = elu1(acc[mt][nt][3]);
            int cout0 = nt*8 + 2*q;
            if (out) {
                if (rA < N_) {
                    size_t oi = ((size_t)w*N_ + rA)*64 + cout0;
                    float2 xv = *(const float2*)&x[oi];
                    *(float2*)&out[oi] = make_float2(c0 + xv.x, c1 + xv.y);
                }
                if (rB < N_) {
                    size_t oi = ((size_t)w*N_ + rB)*64 + cout0;
                    float2 xv = *(const float2*)&x[oi];
                    *(float2*)&out[oi] = make_float2(c2 + xv.x, c3 + xv.y);
                }
            } else {
                if (rA < N_)
                    *(__half2*)&g_Hh[((size_t)w*N_ + rA)*64 + cout0] = __floats2half2_rn(c0, c1);
                if (rB < N_)
                    *(__half2*)&g_Hh[((size_t)w*N_ + rB)*64 + cout0] = __floats2half2_rn(c2, c3);
            }
        }
    }
}

// ---------------- launch -----------------------------------------------------
extern "C" void kernel_launch(void* const* d_in, const int* in_sizes, int n_in,
                              void* d_out, int out_size) {
    const float* x  = (const float*)d_in[0];
    const int*   ei = (const int*)  d_in[1];
    const float* ew = (const float*)d_in[2];

    WPtrs p;
    if (in_sizes[5] == 1024) {
        int idx = 3;
        for (int t = 0; t < 4; t++) {
            p.sw[t] = (const float*)d_in[idx++];
            p.sb[t] = (const float*)d_in[idx++];
            p.gw[t] = (const float*)d_in[idx++];
            p.gb[t] = (const float*)d_in[idx++];
        }
    } else {
        int idx = 3;
        for (int t = 0; t < 4; t++) {
            p.sw[t] = (const float*)d_in[idx++];
            p.sb[t] = (const float*)d_in[idx++];
        }
        for (int t = 0; t < 4; t++) {
            p.gw[t] = (const float*)d_in[idx++];
            p.gb[t] = (const float*)d_in[idx++];
        }
    }
    const float* gw = (const float*)d_in[19];
    const float* gb = (const float*)d_in[20];
    float* out = (float*)d_out;

    static cudaStream_t s2 = nullptr;
    static cudaEvent_t evA = nullptr, evB = nullptr;
    if (!s2) {
        cudaFuncSetAttribute(incep_mma_kernel,
                             cudaFuncAttributeMaxDynamicSharedMemorySize, SMEM_BYTES);
        cudaStreamCreateWithFlags(&s2, cudaStreamNonBlocking);
        cudaEventCreateWithFlags(&evA, cudaEventDisableTiming);
        cudaEventCreateWithFlags(&evB, cudaEventDisableTiming);
    }

    // fork: CSR build on s2, inception chain on main stream
    cudaEventRecord(evA, 0);
    cudaStreamWaitEvent(s2, evA, 0);

    zerodeg_kernel<<<(W_*N_ + 255)/256, 256, 0, s2>>>();
    hist_kernel<<<(W_*E_ + 255)/256, 256, 0, s2>>>(ei);
    scan_kernel<<<W_, 512, 0, s2>>>();
    place_kernel<<<(W_*E_ + 255)/256, 256, 0, s2>>>(ei, ew);
    cudaEventRecord(evB, s2);

    prep_kernel<<<(7*128*64 + 255)/256, 256>>>(p);
    prep_gw_kernel<<<(2*12*8*4*32 + 255)/256, 256>>>(gw);
    pack_x_kernel<<<(W_*N_*8 + 255)/256, 256>>>((const float4*)x);
    incep_mma_kernel<<<N_/16, 256, SMEM_BYTES>>>();

    // join
    cudaStreamWaitEvent(0, evB, 0);

    for (int hop = 0; hop < 2; hop++) {
        agg_kernel<<<W_*N_*8/256, 256>>>();
        gemm_mma_kernel<<<dim3((N_ + 255)/256, W_), 256>>>(gb, hop, x,
                                                           hop == 1 ? out : nullptr);
    }
}